// round 14
// baseline (speedup 1.0000x reference)
#include <cuda_runtime.h>
#include <cuda_bf16.h>
#include <cstdint>

#define BB 8
#define SS 4096
#define TT 512
#define HH 768

// ---------------------------------------------------------------------------
// Scratch. Split bf16: [R, 2C], hi in [0,C), lo in [C,2C).
// seq/tgt buffers COMPACTED per batch; probs/vT2 compacted along t.
// ---------------------------------------------------------------------------
__device__ __align__(16) __nv_bfloat16 g_seq2 [(size_t)BB * SS * 2 * HH];
__device__ __align__(16) __nv_bfloat16 g_tgt2 [(size_t)BB * TT * 2 * HH];
__device__ __align__(16) __nv_bfloat16 g_W2   [(size_t)HH * 2 * HH];
__device__ __align__(16) __nv_bfloat16 g_seqt2[(size_t)BB * SS * 2 * HH];
__device__ __align__(16) __nv_bfloat16 g_tgtt2[(size_t)BB * TT * 2 * HH];
__device__ __align__(16) float         g_logits[(size_t)BB * SS * TT];
__device__ __align__(16) __nv_bfloat16 g_probs2[(size_t)BB * SS * 2 * TT];
__device__ __align__(16) __nv_bfloat16 g_vT2  [(size_t)BB * HH * 2 * TT];
__device__ int   g_idx_s[BB * SS];
__device__ int   g_rnk_s[BB * SS];
__device__ int   g_cnt_s[BB];
__device__ int   g_idx_t[BB * TT];
__device__ int   g_rnk_t[BB * TT];
__device__ int   g_cnt_t[BB];
__device__ float g_cm [BB * HH];
__device__ float g_vm [BB * HH];
__device__ float g_c  [BB * SS];

// ---------------------------------------------------------------------------
// Helpers
// ---------------------------------------------------------------------------
__device__ __forceinline__ uint32_t smem_u32(const void* p) {
    uint32_t a;
    asm("{ .reg .u64 t; cvta.to.shared.u64 t, %1; cvt.u32.u64 %0, t; }" : "=r"(a) : "l"(p));
    return a;
}
__device__ __forceinline__ void cp16(uint32_t saddr, const void* g) {
    asm volatile("cp.async.cg.shared.global [%0], [%1], 16;" :: "r"(saddr), "l"(g) : "memory");
}
#define CP_COMMIT() asm volatile("cp.async.commit_group;" ::: "memory")
template <int N>
__device__ __forceinline__ void cp_wait() {
    asm volatile("cp.async.wait_group %0;" :: "n"(N) : "memory");
}
__device__ __forceinline__ void ldsm_x4(uint32_t* r, uint32_t addr) {
    asm volatile("ldmatrix.sync.aligned.m8n8.x4.shared.b16 {%0,%1,%2,%3}, [%4];"
        : "=r"(r[0]), "=r"(r[1]), "=r"(r[2]), "=r"(r[3]) : "r"(addr));
}
__device__ __forceinline__ void mma_bf16(float* c, const uint32_t* a, const uint32_t* b) {
    asm volatile(
        "mma.sync.aligned.m16n8k16.row.col.f32.bf16.bf16.f32 "
        "{%0,%1,%2,%3}, {%4,%5,%6,%7}, {%8,%9}, {%0,%1,%2,%3};"
        : "+f"(c[0]), "+f"(c[1]), "+f"(c[2]), "+f"(c[3])
        : "r"(a[0]), "r"(a[1]), "r"(a[2]), "r"(a[3]), "r"(b[0]), "r"(b[1]));
}
__device__ __forceinline__ void split1(float x, __nv_bfloat16& h, __nv_bfloat16& l) {
    h = __float2bfloat16(x);
    l = __float2bfloat16(x - __bfloat162float(h));
}

// ---------------------------------------------------------------------------
// Fused compaction for both masks. grid (BB, 2): y=0 seq(SS), y=1 tgt(TT).
// ---------------------------------------------------------------------------
__device__ __forceinline__ void compact_body(const int* m, int* idx, int* rnk,
                                             int* cnt, int L)
{
    const int tid = threadIdx.x;
    const int lane = tid & 31, w = tid >> 5;

    int v[4], c = 0;
    #pragma unroll
    for (int i = 0; i < 4; i++) {
        const int p = tid * 4 + i;
        v[i] = (p < L) ? m[p] : 0;
        c += v[i];
    }
    int sc = c;
    #pragma unroll
    for (int o = 1; o < 32; o <<= 1) {
        int t = __shfl_up_sync(0xffffffffu, sc, o);
        if (lane >= o) sc += t;
    }
    __shared__ int ws[32];
    if (lane == 31) ws[w] = sc;
    __syncthreads();
    if (w == 0) {
        int t = ws[lane];
        #pragma unroll
        for (int o = 1; o < 32; o <<= 1) {
            int u = __shfl_up_sync(0xffffffffu, t, o);
            if (lane >= o) t += u;
        }
        ws[lane] = t;
    }
    __syncthreads();
    int base = sc - c + (w ? ws[w - 1] : 0);
    #pragma unroll
    for (int i = 0; i < 4; i++) {
        const int p = tid * 4 + i;
        if (p < L) {
            if (v[i]) { idx[base] = p; rnk[p] = base; base++; }
            else      { rnk[p] = -1; }
        }
    }
    if (tid == 0) *cnt = ws[31];
}

__global__ void compact_both(const int* __restrict__ smask, const int* __restrict__ tmask,
                             int* __restrict__ idx_s, int* __restrict__ rnk_s,
                             int* __restrict__ cnt_s,
                             int* __restrict__ idx_t, int* __restrict__ rnk_t,
                             int* __restrict__ cnt_t)
{
    const int b = blockIdx.x;
    if (blockIdx.y == 0)
        compact_body(smask + (long)b * SS, idx_s + (long)b * SS, rnk_s + (long)b * SS,
                     cnt_s + b, SS);
    else
        compact_body(tmask + (long)b * TT, idx_t + (long)b * TT, rnk_t + (long)b * TT,
                     cnt_t + b, TT);
}

// ---------------------------------------------------------------------------
// seq pass (R12 version): cat first half + compacted split seq2.
// ---------------------------------------------------------------------------
__launch_bounds__(256)
__global__ void seq_prep(const float* __restrict__ seq, const int* __restrict__ rnk,
                         float* __restrict__ cat, __nv_bfloat16* __restrict__ out)
{
    const long t = (long)blockIdx.x * 256 + threadIdx.x;
    const long total = (long)BB * SS * (HH / 4);
    if (t >= total) return;
    const long row = t / (HH / 4);
    const int c4 = (int)(t % (HH / 4));
    const int b = (int)(row >> 12);
    const int r = rnk[row];
    float4 v = reinterpret_cast<const float4*>(seq)[row * (HH / 4) + c4];
    if (r < 0) {
        reinterpret_cast<float4*>(cat)[row * (2 * HH / 4) + c4] = make_float4(0, 0, 0, 0);
        return;
    }
    reinterpret_cast<float4*>(cat)[row * (2 * HH / 4) + c4] = v;
    __nv_bfloat16 h0, l0, h1, l1, h2, l2, h3, l3;
    split1(v.x, h0, l0); split1(v.y, h1, l1); split1(v.z, h2, l2); split1(v.w, h3, l3);
    __nv_bfloat16* oh = out + ((long)b * SS + r) * 2L * HH + c4 * 4;
    __nv_bfloat16* ol = oh + HH;
    reinterpret_cast<__nv_bfloat162*>(oh)[0] = __nv_bfloat162(h0, h1);
    reinterpret_cast<__nv_bfloat162*>(oh)[1] = __nv_bfloat162(h2, h3);
    reinterpret_cast<__nv_bfloat162*>(ol)[0] = __nv_bfloat162(l0, l1);
    reinterpret_cast<__nv_bfloat162*>(ol)[1] = __nv_bfloat162(l2, l3);
}

// ---------------------------------------------------------------------------
// tgt pass: compacted tgt2 AND compacted vT2 (R12 version).
// ---------------------------------------------------------------------------
__global__ void tgtv_prep(const float* __restrict__ V, const int* __restrict__ rnk,
                          __nv_bfloat16* __restrict__ tgt2, __nv_bfloat16* __restrict__ vT2)
{
    __shared__ float tile[32][33];
    const int b = blockIdx.z;
    const int t0 = blockIdx.x * 32, h0 = blockIdx.y * 32;
    const int tx = threadIdx.x, ty = threadIdx.y;
    #pragma unroll
    for (int i = 0; i < 32; i += 8)
        tile[ty + i][tx] = V[((long)b * TT + t0 + ty + i) * HH + h0 + tx];
    __syncthreads();
    #pragma unroll
    for (int i = 0; i < 32; i += 8) {
        const int h = h0 + ty + i, t = t0 + tx;
        const int j = rnk[(long)b * TT + t];
        if (j >= 0) {
            __nv_bfloat16 hh, ll;
            split1(tile[tx][ty + i], hh, ll);
            const long base = ((long)b * HH + h) * (2L * TT) + j;
            vT2[base] = hh; vT2[base + TT] = ll;
        }
    }
    #pragma unroll
    for (int i = 0; i < 32; i += 8) {
        const int t = t0 + ty + i;
        const int j = rnk[(long)b * TT + t];
        if (j >= 0) {
            __nv_bfloat16 hh, ll;
            split1(tile[ty + i][tx], hh, ll);
            __nv_bfloat16* o = tgt2 + ((long)b * TT + j) * 2L * HH + h0 + tx;
            o[0] = hh; o[HH] = ll;
        }
    }
}

// ---------------------------------------------------------------------------
// Zero pads: y=0 seq2 rows, y=1 tgt2 rows, y=2 vT2 pad columns.
// ---------------------------------------------------------------------------
__global__ void zero_pad(const int* __restrict__ cnt_s, const int* __restrict__ cnt_t,
                         __nv_bfloat16* __restrict__ seq2, __nv_bfloat16* __restrict__ tgt2,
                         __nv_bfloat16* __restrict__ vT2)
{
    const int b = blockIdx.x;
    if (blockIdx.y == 2) {
        const int c = cnt_t[b];
        const int kpad = (c + 127) & ~127;
        const int padw = min(kpad, TT) - c;
        if (padw <= 0) return;
        const long total = (long)HH * 2 * padw;
        for (long i = (long)blockIdx.z * 256 + threadIdx.x; i < total;
             i += (long)gridDim.z * 256) {
            const int h = (int)(i / (2 * padw));
            const int r = (int)(i % (2 * padw));
            const int sl = r / padw, off = r % padw;
            vT2[((long)b * HH + h) * (2L * TT) + (long)sl * TT + c + off] = __nv_bfloat16(0.f);
        }
        return;
    }
    int c, L;
    __nv_bfloat16* buf;
    if (blockIdx.y == 0) { c = cnt_s[b]; L = SS; buf = seq2 + (long)b * SS * 2 * HH; }
    else                 { c = cnt_t[b]; L = TT; buf = tgt2 + (long)b * TT * 2 * HH; }
    const int e = min((c + 127) & ~127, L);
    const long nU4 = (long)(e - c) * (2 * HH / 8);
    uint4* base = reinterpret_cast<uint4*>(buf + (long)c * 2 * HH);
    const uint4 z = make_uint4(0, 0, 0, 0);
    for (long i = (long)blockIdx.z * 256 + threadIdx.x; i < nU4; i += (long)gridDim.z * 256)
        base[i] = z;
}

// ---------------------------------------------------------------------------
// W: fp32 -> split bf16
// ---------------------------------------------------------------------------
__launch_bounds__(256)
__global__ void split_plain(const float* __restrict__ in, __nv_bfloat16* __restrict__ out,
                            int R, int C)
{
    const long idx = (long)blockIdx.x * blockDim.x + threadIdx.x;
    const long total = (long)R * C / 4;
    if (idx >= total) return;
    const long row = idx / (C / 4);
    const int c4 = (int)(idx % (C / 4));
    float4 v = reinterpret_cast<const float4*>(in)[idx];
    __nv_bfloat16 h0, l0, h1, l1, h2, l2, h3, l3;
    split1(v.x, h0, l0); split1(v.y, h1, l1); split1(v.z, h2, l2); split1(v.w, h3, l3);
    __nv_bfloat16* oh = out + row * 2L * C + c4 * 4;
    __nv_bfloat16* ol = oh + C;
    reinterpret_cast<__nv_bfloat162*>(oh)[0] = __nv_bfloat162(h0, h1);
    reinterpret_cast<__nv_bfloat162*>(oh)[1] = __nv_bfloat162(h2, h3);
    reinterpret_cast<__nv_bfloat162*>(ol)[0] = __nv_bfloat162(l0, l1);
    reinterpret_cast<__nv_bfloat162*>(ol)[1] = __nv_bfloat162(l2, l3);
}

// ---------------------------------------------------------------------------
// colstat: cm = (1/T) sum_all V;  vm = sum over MASKED t of V.
// ---------------------------------------------------------------------------
__launch_bounds__(256)
__global__ void colstat(const float* __restrict__ V, const int* __restrict__ tmask,
                        float* __restrict__ cm, float* __restrict__ vm)
{
    const int t = blockIdx.x * 256 + threadIdx.x;
    if (t >= BB * HH) return;
    const int b = t / HH, h = t % HH;
    const float* p = V + (long)b * TT * HH + h;
    const int* m = tmask + (long)b * TT;
    float sa = 0.f, sm_ = 0.f;
    #pragma unroll 4
    for (int i = 0; i < TT; i++) {
        const float x = p[(long)i * HH];
        sa += x;
        if (!m[i]) sm_ += x;
    }
    cm[t] = sa * (1.0f / TT);
    vm[t] = sm_;
}

// ---------------------------------------------------------------------------
// Masked seq rows: attn_out = colmean, cat second half = 0 (R12 version).
// ---------------------------------------------------------------------------
__launch_bounds__(256)
__global__ void fill_masked(const int* __restrict__ mask, const float* __restrict__ cm,
                            float* __restrict__ cat, float* __restrict__ attn, int writeAttn)
{
    const long t = (long)blockIdx.x * 256 + threadIdx.x;
    const long total = (long)BB * SS * (HH / 4);
    if (t >= total) return;
    const long row = t / (HH / 4);
    const int c4 = (int)(t % (HH / 4));
    if (mask[row]) return;
    const int b = (int)(row >> 12);
    float4 v = reinterpret_cast<const float4*>(cm)[(long)b * (HH / 4) + c4];
    if (writeAttn)
        reinterpret_cast<float4*>(attn)[row * (HH / 4) + c4] = v;
    reinterpret_cast<float4*>(cat)[row * (2 * HH / 4) + (HH / 4) + c4] = make_float4(0, 0, 0, 0);
}

// ---------------------------------------------------------------------------
// 512-thread GEMM for the merged X @ W^T (EPI0 only). CTA tile 128x256,
// 16 warps (2m x 8n), warp tile 64x32 (proven shape), smem 144KB (1 CTA/SM,
// 16 warps/SM — same warp occupancy as 2x256-thread CTAs). Halves A re-reads
// (x-blocks 6 -> 3) and B smem-store traffic vs the 128x128 version.
// ---------------------------------------------------------------------------
__launch_bounds__(512)
__global__ void gemm_xw(const __nv_bfloat16* __restrict__ A,      // seq2
                        const __nv_bfloat16* __restrict__ W2,     // [HH, 2*HH]
                        const __nv_bfloat16* __restrict__ A2,     // tgt2
                        __nv_bfloat16* __restrict__ obf,          // seqt2
                        __nv_bfloat16* __restrict__ obf2,         // tgtt2
                        int ySplit,
                        const int* __restrict__ cnt_s, const int* __restrict__ cnt_t)
{
    extern __shared__ char smem[];
    const uint32_t sb = smem_u32(smem);

    const int tid = threadIdx.x;
    const int wid = tid >> 5;
    const int lane = tid & 31;

    const long Kr = 2L * HH;

    const __nv_bfloat16* Ab;
    __nv_bfloat16* obf_sel;
    long orow;
    int m0;
    if ((int)blockIdx.y < ySplit) {
        const int b = blockIdx.y >> 5;              // 32 y-blocks/batch (SS/128)
        m0 = (blockIdx.y & 31) * 128;
        if (m0 >= cnt_s[b]) return;
        Ab = A + (long)b * ((long)SS * 2 * HH);
        orow = (long)b * SS;
        obf_sel = obf;
    } else {
        const int yy = (int)blockIdx.y - ySplit;
        const int b = yy >> 2;                      // 4 y-blocks/batch (TT/128)
        m0 = (yy & 3) * 128;
        if (m0 >= cnt_t[b]) return;
        Ab = A2 + (long)b * ((long)TT * 2 * HH);
        orow = (long)b * TT;
        obf_sel = obf2;
    }
    const int n0 = blockIdx.x * 256;

    const int kc = HH >> 6;      // 12
    const int nk = 3 * kc;       // 36

    const int vr0 = tid >> 3;            // 0..63
    const int vc16 = (tid & 7) * 16;

#define LDG_STAGE0(IT, S)                                                         \
    {                                                                             \
        int _it = (IT);                                                           \
        int _seg = (_it >= 2 * kc) ? 2 : ((_it >= kc) ? 1 : 0);                   \
        int _kl = _it - _seg * kc;                                                \
        long _aC = ((_seg == 1) ? HH : 0) + (long)_kl * 64 + (vc16 >> 1);         \
        long _bC = ((_seg == 2) ? HH : 0) + (long)_kl * 64 + (vc16 >> 1);         \
        uint32_t _sA = sb + (S) * 49152u;                                         \
        uint32_t _sB = _sA + 16384u;                                              \
        _Pragma("unroll")                                                         \
        for (int i = 0; i < 2; i++) {                                             \
            int r = vr0 + 64 * i;                                                 \
            uint32_t sw = (uint32_t)(r * 128 + (vc16 ^ ((r & 7) << 4)));          \
            cp16(_sA + sw, Ab + (long)(m0 + r) * Kr + _aC);                       \
        }                                                                         \
        _Pragma("unroll")                                                         \
        for (int i = 0; i < 4; i++) {                                             \
            int r = vr0 + 64 * i;                                                 \
            uint32_t sw = (uint32_t)(r * 128 + (vc16 ^ ((r & 7) << 4)));          \
            cp16(_sB + sw, W2 + (long)(n0 + r) * Kr + _bC);                       \
        }                                                                         \
    }

    LDG_STAGE0(0, 0); CP_COMMIT();
    LDG_STAGE0(1, 1); CP_COMMIT();

    const int wm = wid & 1;      // 0..1 -> 64 rows
    const int wn = wid >> 1;     // 0..7 -> 32 cols

    float acc[4][4][4] = {};

    const int arow = wm * 64 + (lane & 15);
    const int akb = (lane >> 4) * 16;
    const int brow = wn * 32 + (lane & 7) + ((lane >> 4) * 8);
    const int bkb = ((lane >> 3) & 1) * 16;

    for (int it = 0; it < nk; it++) {
        if (it + 1 < nk) cp_wait<1>(); else cp_wait<0>();
        __syncthreads();

        const uint32_t stA = sb + (uint32_t)(it % 3) * 49152u;
        const uint32_t stB = stA + 16384u;

        #pragma unroll
        for (int ks = 0; ks < 4; ks++) {
            uint32_t afr[4][4], bfr[2][4];
            #pragma unroll
            for (int mt = 0; mt < 4; mt++) {
                const int row = arow + mt * 16;
                ldsm_x4(afr[mt], stA + row * 128 + ((ks * 32 + akb) ^ ((row & 7) << 4)));
            }
            #pragma unroll
            for (int ntp = 0; ntp < 2; ntp++) {
                const int row = brow + ntp * 16;
                ldsm_x4(bfr[ntp], stB + row * 128 + ((ks * 32 + bkb) ^ ((row & 7) << 4)));
            }
            #pragma unroll
            for (int mt = 0; mt < 4; mt++)
                #pragma unroll
                for (int nt = 0; nt < 4; nt++)
                    mma_bf16(acc[mt][nt], afr[mt], &bfr[nt >> 1][(nt & 1) * 2]);
        }

        if (it + 2 < nk) { LDG_STAGE0(it + 2, (it + 2) % 3); CP_COMMIT(); }
    }

    const int er = wm * 64 + (lane >> 2);
    const int ec = wn * 32 + (lane & 3) * 2;
    const int Nout = HH;

    #pragma unroll
    for (int mt = 0; mt < 4; mt++)
        #pragma unroll
        for (int nt = 0; nt < 4; nt++)
            #pragma unroll
            for (int h = 0; h < 2; h++) {
                const long row = orow + m0 + er + mt * 16 + h * 8;
                const int col = n0 + ec + nt * 8;
                float x0 = fmaxf(acc[mt][nt][2 * h], 0.f);
                float x1 = fmaxf(acc[mt][nt][2 * h + 1], 0.f);
                __nv_bfloat16 h0, l0, h1, l1;
                split1(x0, h0, l0); split1(x1, h1, l1);
                __nv_bfloat16* oh = obf_sel + row * 2 * Nout + col;
                *reinterpret_cast<__nv_bfloat162*>(oh) = __nv_bfloat162(h0, h1);
                *reinterpret_cast<__nv_bfloat162*>(oh + Nout) = __nv_bfloat162(l0, l1);
            }
#undef LDG_STAGE0
}

// ---------------------------------------------------------------------------
// 256-thread HMMA GEMM for EPI1 (logits) and EPI2 (P@V + rank-1) — R12-proven.
// ---------------------------------------------------------------------------
template <int EPI>
__launch_bounds__(256)
__global__ void gemm_mma(const __nv_bfloat16* __restrict__ A,
                         const __nv_bfloat16* __restrict__ Bm,
                         long aBatch, long bBatch, int C,
                         float* __restrict__ out0, float* __restrict__ out1,
                         int writeAttn,
                         const int* __restrict__ cntp, const int* __restrict__ cnt2p,
                         const int* __restrict__ idxp,
                         const float* __restrict__ cvec, const float* __restrict__ vmsum)
{
    extern __shared__ char smem[];
    const uint32_t sb = smem_u32(smem);

    const int tid = threadIdx.x;
    const int wid = tid >> 5;
    const int lane = tid & 31;

    const int z = blockIdx.z;
    const long Kr = 2L * C;

    const int m0 = blockIdx.y * 128;
    const int cb = cntp[z];
    if (m0 >= cb) return;
    if (EPI == 1 && (int)blockIdx.x * 128 >= cnt2p[z]) return;
    const __nv_bfloat16* Ab = A + (long)z * aBatch;
    const int n0 = blockIdx.x * 128;
    const __nv_bfloat16* Bb = Bm + (long)z * bBatch;

    int kc;
    if (EPI == 2) kc = (cnt2p[z] + 63) >> 6;
    else          kc = C >> 6;
    const int nk = 3 * kc;

    const int vr0 = tid >> 3;
    const int vc16 = (tid & 7) * 16;

#define LDG_STAGE(IT, S)                                                          \
    {                                                                             \
        int _it = (IT);                                                           \
        int _seg = (_it >= 2 * kc) ? 2 : ((_it >= kc) ? 1 : 0);                   \
        int _kl = _it - _seg * kc;                                                \
        long _aC = ((_seg == 1) ? C : 0) + (long)_kl * 64 + (vc16 >> 1);          \
        long _bC = ((_seg == 2) ? C : 0) + (long)_kl * 64 + (vc16 >> 1);          \
        uint32_t _sA = sb + (S) * 32768u;                                         \
        uint32_t _sB = _sA + 16384u;                                              \
        _Pragma("unroll")                                                         \
        for (int i = 0; i < 4; i++) {                                             \
            int r = vr0 + 32 * i;                                                 \
            uint32_t sw = (uint32_t)(r * 128 + (vc16 ^ ((r & 7) << 4)));          \
            cp16(_sA + sw, Ab + (long)(m0 + r) * Kr + _aC);                       \
            cp16(_sB + sw, Bb + (long)(n0 + r) * Kr + _bC);                       \
        }                                                                         \
    }

    LDG_STAGE(0, 0); CP_COMMIT();
    LDG_STAGE(1, 1); CP_COMMIT();

    const int wm = wid & 1;
    const int wn = wid >> 1;

    float acc[4][4][4] = {};

    const int arow = wm * 64 + (lane & 15);
    const int akb = (lane >> 4) * 16;
    const int brow = wn * 32 + (lane & 7) + ((lane >> 4) * 8);
    const int bkb = ((lane >> 3) & 1) * 16;

    for (int it = 0; it < nk; it++) {
        if (it + 1 < nk) cp_wait<1>(); else cp_wait<0>();
        __syncthreads();

        const uint32_t stA = sb + (uint32_t)(it % 3) * 32768u;
        const uint32_t stB = stA + 16384u;

        #pragma unroll
        for (int ks = 0; ks < 4; ks++) {
            uint32_t afr[4][4], bfr[2][4];
            #pragma unroll
            for (int mt = 0; mt < 4; mt++) {
                const int row = arow + mt * 16;
                ldsm_x4(afr[mt], stA + row * 128 + ((ks * 32 + akb) ^ ((row & 7) << 4)));
            }
            #pragma unroll
            for (int ntp = 0; ntp < 2; ntp++) {
                const int row = brow + ntp * 16;
                ldsm_x4(bfr[ntp], stB + row * 128 + ((ks * 32 + bkb) ^ ((row & 7) << 4)));
            }
            #pragma unroll
            for (int mt = 0; mt < 4; mt++)
                #pragma unroll
                for (int nt = 0; nt < 4; nt++)
                    mma_bf16(acc[mt][nt], afr[mt], &bfr[nt >> 1][(nt & 1) * 2]);
        }

        if (it + 2 < nk) { LDG_STAGE(it + 2, (it + 2) % 3); CP_COMMIT(); }
    }

    const int er = wm * 64 + (lane >> 2);
    const int ec = wn * 32 + (lane & 3) * 2;

    if (EPI == 1) {
        #pragma unroll
        for (int mt = 0; mt < 4; mt++)
            #pragma unroll
            for (int nt = 0; nt < 4; nt++)
                #pragma unroll
                for (int h = 0; h < 2; h++) {
                    const int row = m0 + er + mt * 16 + h * 8;
                    const int col = n0 + ec + nt * 8;
                    float2 v = make_float2(acc[mt][nt][2 * h], acc[mt][nt][2 * h + 1]);
                    *reinterpret_cast<float2*>(out0 + ((long)z * SS + row) * TT + col) = v;
                }
    } else {
        const long zb = (long)z * SS;
        #pragma unroll
        for (int mt = 0; mt < 4; mt++)
            #pragma unroll
            for (int h = 0; h < 2; h++) {
                const int local = m0 + er + mt * 16 + h * 8;
                if (local < cb) {
                    const float cr = cvec[zb + local];
                    const long gs = zb + idxp[zb + local];
                    #pragma unroll
                    for (int nt = 0; nt < 4; nt++) {
                        const int col = n0 + ec + nt * 8;
                        const float2 w = *reinterpret_cast<const float2*>(
                            vmsum + (long)z * HH + col);
                        float2 v = make_float2(acc[mt][nt][2 * h] + cr * w.x,
                                               acc[mt][nt][2 * h + 1] + cr * w.y);
                        if (writeAttn)
                            *reinterpret_cast<float2*>(out1 + gs * (long)HH + col) = v;
                        *reinterpret_cast<float2*>(out0 + gs * (long)(2 * HH) + HH + col) = v;
                    }
                }
            }
    }
#undef LDG_STAGE
}

// ---------------------------------------------------------------------------
// Softmax on compacted logits (R12 version).
// ---------------------------------------------------------------------------
__launch_bounds__(128)
__global__ void softmax_c(const float* __restrict__ logits, __nv_bfloat16* __restrict__ P2,
                          float* __restrict__ cvec,
                          const int* __restrict__ cnt_s, const int* __restrict__ cnt_t)
{
    const long row = blockIdx.x;
    const int b = (int)(row >> 12);
    if ((int)(row & (SS - 1)) >= cnt_s[b]) return;
    const int ct = cnt_t[b];
    const int kpad = (ct + 63) & ~63;
    const float* p = logits + row * TT;
    const int tid = threadIdx.x;
    const int warp = tid >> 5, lane = tid & 31;

    float v[4];
    #pragma unroll
    for (int i = 0; i < 4; i++) {
        const int j = tid + 128 * i;
        v[i] = (j < ct) ? p[j] : -1e30f;
    }

    float mx = fmaxf(fmaxf(v[0], v[1]), fmaxf(v[2], v[3]));
    #pragma unroll
    for (int o = 16; o > 0; o >>= 1) mx = fmaxf(mx, __shfl_xor_sync(0xffffffffu, mx, o));
    __shared__ float smx[4];
    if (lane == 0) smx[warp] = mx;
    __syncthreads();
    mx = fmaxf(fmaxf(smx[0], smx[1]), fmaxf(smx[2], smx[3]));
    if (ct < TT) mx = fmaxf(mx, 0.0f);

    float sum = 0.f;
    #pragma unroll
    for (int i = 0; i < 4; i++) {
        const int j = tid + 128 * i;
        if (j < ct) { v[i] = __expf(v[i] - mx); sum += v[i]; }
    }
    #pragma unroll
    for (int o = 16; o > 0; o >>= 1) sum += __shfl_xor_sync(0xffffffffu, sum, o);
    __shared__ float ssum[4];
    if (lane == 0) ssum[warp] = sum;
    __syncthreads();
    const float em = __expf(-mx);
    const float inv = 1.0f / (ssum[0] + ssum[1] + ssum[2] + ssum[3] + (float)(TT - ct) * em);

    if (tid == 0) cvec[row] = em * inv;

    __nv_bfloat16* out = P2 + row * 2L * TT;
    #pragma unroll
    for (int i = 0; i < 4; i++) {
        const int j = tid + 128 * i;
        if (j < ct) {
            __nv_bfloat16 h, l;
            split1(v[i] * inv, h, l);
            out[j] = h; out[TT + j] = l;
        } else if (j < kpad) {
            out[j] = __nv_bfloat16(0.f); out[TT + j] = __nv_bfloat16(0.f);
        }
    }
}

// ---------------------------------------------------------------------------

extern "C" void kernel_launch(void* const* d_in, const int* in_sizes, int n_in,
                              void* d_out, int out_size)
{
    const float* seq   = (const float*)d_in[0];
    const int*   smask = (const int*)d_in[1];
    const float* tgt   = (const float*)d_in[2];
    const int*   tmask = (const int*)d_in[3];
    const float* W     = (const float*)d_in[4];
    float* out = (float*)d_out;

    __nv_bfloat16 *p_seq2, *p_tgt2, *p_W2, *p_seqt2, *p_tgtt2, *p_probs2, *p_vT2;
    float *p_logits, *p_cm, *p_vm, *p_c;
    int *p_idx_s, *p_rnk_s, *p_cnt_s, *p_idx_t, *p_rnk_t, *p_cnt_t;
    cudaGetSymbolAddress((void**)&p_seq2, g_seq2);
    cudaGetSymbolAddress((void**)&p_tgt2, g_tgt2);
    cudaGetSymbolAddress((void**)&p_W2, g_W2);
    cudaGetSymbolAddress((void**)&p_seqt2, g_seqt2);
    cudaGetSymbolAddress((void**)&p_tgtt2, g_tgtt2);
    cudaGetSymbolAddress((void**)&p_logits, g_logits);
    cudaGetSymbolAddress((void**)&p_probs2, g_probs2);
    cudaGetSymbolAddress((void**)&p_vT2, g_vT2);
    cudaGetSymbolAddress((void**)&p_idx_s, g_idx_s);
    cudaGetSymbolAddress((void**)&p_rnk_s, g_rnk_s);
    cudaGetSymbolAddress((void**)&p_cnt_s, g_cnt_s);
    cudaGetSymbolAddress((void**)&p_idx_t, g_idx_t);
    cudaGetSymbolAddress((void**)&p_rnk_t, g_rnk_t);
    cudaGetSymbolAddress((void**)&p_cnt_t, g_cnt_t);
    cudaGetSymbolAddress((void**)&p_cm, g_cm);
    cudaGetSymbolAddress((void**)&p_vm, g_vm);
    cudaGetSymbolAddress((void**)&p_c, g_c);

    const int write_attn = (out_size >= BB * SS * 3 * HH) ? 1 : 0;
    float* out_attn = out + (size_t)BB * SS * 2 * HH;

    const int SMEM_256 = 3 * 32768;   // 96KB
    const int SMEM_512 = 3 * 49152;   // 144KB
    cudaFuncSetAttribute(gemm_xw, cudaFuncAttributeMaxDynamicSharedMemorySize, SMEM_512);
    cudaFuncSetAttribute(gemm_mma<1>, cudaFuncAttributeMaxDynamicSharedMemorySize, SMEM_256);
    cudaFuncSetAttribute(gemm_mma<2>, cudaFuncAttributeMaxDynamicSharedMemorySize, SMEM_256);

    const int NCHUNK_S = (BB * SS * (HH / 4) + 255) / 256;

    // 0) compaction + column stats + operand prep
    compact_both<<<dim3(BB, 2), 1024>>>(smask, tmask, p_idx_s, p_rnk_s, p_cnt_s,
                                        p_idx_t, p_rnk_t, p_cnt_t);
    seq_prep<<<NCHUNK_S, 256>>>(seq, p_rnk_s, out, p_seq2);
    tgtv_prep<<<dim3(TT / 32, HH / 32, BB), dim3(32, 8)>>>(tgt, p_rnk_t, p_tgt2, p_vT2);
    zero_pad<<<dim3(BB, 3, 8), 256>>>(p_cnt_s, p_cnt_t, p_seq2, p_tgt2, p_vT2);
    split_plain<<<(HH * HH / 4 + 255) / 256, 256>>>(W, p_W2, HH, HH);
    colstat<<<(BB * HH + 255) / 256, 256>>>(tgt, tmask, p_cm, p_vm);

    // 1+2 merged) seq_t AND tgt_t = relu(X @ W^T): 512-thread 128x256 CTAs
    const int Y_SEQ = (BB * SS) / 128;   // 256
    const int Y_TGT = (BB * TT) / 128;   // 32
    gemm_xw<<<dim3(HH / 256, Y_SEQ + Y_TGT, 1), 512, SMEM_512>>>(
        p_seq2, p_W2, p_tgt2, p_seqt2, p_tgtt2, Y_SEQ, p_cnt_s, p_cnt_t);

    // 3) logits = seq_t @ tgt_t^T (rows AND cols compacted)
    gemm_mma<1><<<dim3(TT / 128, SS / 128, BB), 256, SMEM_256>>>(
        p_seqt2, p_tgtt2, (long)SS * 2 * HH, (long)TT * 2 * HH, HH,
        p_logits, nullptr, 0, p_cnt_s, p_cnt_t, nullptr, nullptr, nullptr);

    // 4) softmax on compacted logits; emits compacted probs + c
    softmax_c<<<BB * SS, 128>>>(p_logits, p_probs2, p_c, p_cnt_s, p_cnt_t);

    // 5) attn_out = P_compact @ V_compact + c * Vm (rank-1), scatter rows
    gemm_mma<2><<<dim3(HH / 128, SS / 128, BB), 256, SMEM_256>>>(
        p_probs2, p_vT2, (long)SS * 2 * TT, (long)HH * 2 * TT, TT,
        out, out_attn, write_attn, p_cnt_s, p_cnt_t, p_idx_s, p_c, p_vm);

    // 6) masked seq rows: attn = colmean(V), cat second half = 0
    fill_masked<<<NCHUNK_S, 256>>>(smask, p_cm, out, out_attn, write_attn);
}

// round 15
// speedup vs baseline: 1.1158x; 1.1158x over previous
#include <cuda_runtime.h>
#include <cuda_bf16.h>
#include <cstdint>

#define BB 8
#define SS 4096
#define TT 512
#define HH 768

// ---------------------------------------------------------------------------
// Scratch. Split bf16: [R, 2C], hi in [0,C), lo in [C,2C).
// seq/tgt buffers COMPACTED per batch; probs/vT2 compacted along t.
// rnk encoding: unmasked -> compact slot j >= 0; masked -> -(padslot)-1 where
// padslot enumerates [cnt, L) uniquely (used to zero GEMM pad rows/cols).
// ---------------------------------------------------------------------------
__device__ __align__(16) __nv_bfloat16 g_seq2 [(size_t)BB * SS * 2 * HH];
__device__ __align__(16) __nv_bfloat16 g_tgt2 [(size_t)BB * TT * 2 * HH];
__device__ __align__(16) __nv_bfloat16 g_W2   [(size_t)HH * 2 * HH];
__device__ __align__(16) __nv_bfloat16 g_seqt2[(size_t)BB * SS * 2 * HH];
__device__ __align__(16) __nv_bfloat16 g_tgtt2[(size_t)BB * TT * 2 * HH];
__device__ __align__(16) float         g_logits[(size_t)BB * SS * TT];
__device__ __align__(16) __nv_bfloat16 g_probs2[(size_t)BB * SS * 2 * TT];
__device__ __align__(16) __nv_bfloat16 g_vT2  [(size_t)BB * HH * 2 * TT];
__device__ int   g_idx_s[BB * SS];
__device__ int   g_rnk_s[BB * SS];
__device__ int   g_cnt_s[BB];
__device__ int   g_idx_t[BB * TT];
__device__ int   g_rnk_t[BB * TT];
__device__ int   g_cnt_t[BB];
__device__ float g_cm [BB * HH];    // (1/T)*sum_all_t V
__device__ float g_vm [BB * HH];    // sum_masked_t V
__device__ float g_c  [BB * SS];    // per compact seq row: masked-t prob

// ---------------------------------------------------------------------------
// Helpers
// ---------------------------------------------------------------------------
__device__ __forceinline__ uint32_t smem_u32(const void* p) {
    uint32_t a;
    asm("{ .reg .u64 t; cvta.to.shared.u64 t, %1; cvt.u32.u64 %0, t; }" : "=r"(a) : "l"(p));
    return a;
}
__device__ __forceinline__ void cp16(uint32_t saddr, const void* g) {
    asm volatile("cp.async.cg.shared.global [%0], [%1], 16;" :: "r"(saddr), "l"(g) : "memory");
}
#define CP_COMMIT() asm volatile("cp.async.commit_group;" ::: "memory")
template <int N>
__device__ __forceinline__ void cp_wait() {
    asm volatile("cp.async.wait_group %0;" :: "n"(N) : "memory");
}
__device__ __forceinline__ void ldsm_x4(uint32_t* r, uint32_t addr) {
    asm volatile("ldmatrix.sync.aligned.m8n8.x4.shared.b16 {%0,%1,%2,%3}, [%4];"
        : "=r"(r[0]), "=r"(r[1]), "=r"(r[2]), "=r"(r[3]) : "r"(addr));
}
__device__ __forceinline__ void mma_bf16(float* c, const uint32_t* a, const uint32_t* b) {
    asm volatile(
        "mma.sync.aligned.m16n8k16.row.col.f32.bf16.bf16.f32 "
        "{%0,%1,%2,%3}, {%4,%5,%6,%7}, {%8,%9}, {%0,%1,%2,%3};"
        : "+f"(c[0]), "+f"(c[1]), "+f"(c[2]), "+f"(c[3])
        : "r"(a[0]), "r"(a[1]), "r"(a[2]), "r"(a[3]), "r"(b[0]), "r"(b[1]));
}
__device__ __forceinline__ void split1(float x, __nv_bfloat16& h, __nv_bfloat16& l) {
    h = __float2bfloat16(x);
    l = __float2bfloat16(x - __bfloat162float(h));
}

// ---------------------------------------------------------------------------
// Per-batch ordered compaction: idx (compact->orig), cnt, and rnk with the
// masked-pad-slot encoding described above.
// ---------------------------------------------------------------------------
__global__ void compact_index(const int* __restrict__ mask, int* __restrict__ idx,
                              int* __restrict__ rnk, int* __restrict__ cnt, int L)
{
    const int b = blockIdx.x;
    const int tid = threadIdx.x;
    const int lane = tid & 31, w = tid >> 5;
    const int* m = mask + (long)b * L;

    int v[4], c = 0;
    #pragma unroll
    for (int i = 0; i < 4; i++) {
        const int p = tid * 4 + i;
        v[i] = (p < L) ? m[p] : 0;
        c += v[i];
    }
    int sc = c;
    #pragma unroll
    for (int o = 1; o < 32; o <<= 1) {
        int t = __shfl_up_sync(0xffffffffu, sc, o);
        if (lane >= o) sc += t;
    }
    __shared__ int ws[32];
    if (lane == 31) ws[w] = sc;
    __syncthreads();
    if (w == 0) {
        int t = ws[lane];
        #pragma unroll
        for (int o = 1; o < 32; o <<= 1) {
            int u = __shfl_up_sync(0xffffffffu, t, o);
            if (lane >= o) t += u;
        }
        ws[lane] = t;
    }
    __syncthreads();
    int base = sc - c + (w ? ws[w - 1] : 0);   // unmasked before p
    const int total = ws[31];
    #pragma unroll
    for (int i = 0; i < 4; i++) {
        const int p = tid * 4 + i;
        if (p < L) {
            if (v[i]) { idx[(long)b * L + base] = p; rnk[(long)b * L + p] = base; base++; }
            else {
                // masked: pad slot = cnt + (#masked before p) = total + (p - base)
                rnk[(long)b * L + p] = -(total + (p - base)) - 1;
            }
        }
    }
    if (tid == 0) cnt[b] = total;
}

// ---------------------------------------------------------------------------
// Fused seq pass: one read of seq -> masked fp32 cat first half + compacted
// split seq2. Masked rows additionally zero their assigned pad slot (only
// within the ceil128 region the GEMM reads) — replaces zero_pad for seq2.
// ---------------------------------------------------------------------------
__launch_bounds__(256)
__global__ void seq_prep(const float* __restrict__ seq, const int* __restrict__ rnk,
                         const int* __restrict__ cnt_s,
                         float* __restrict__ cat, __nv_bfloat16* __restrict__ out)
{
    const long t = (long)blockIdx.x * 256 + threadIdx.x;
    const long total = (long)BB * SS * (HH / 4);
    if (t >= total) return;
    const long row = t / (HH / 4);
    const int c4 = (int)(t % (HH / 4));
    const int b = (int)(row >> 12);
    const int r = rnk[row];
    if (r < 0) {
        reinterpret_cast<float4*>(cat)[row * (2 * HH / 4) + c4] = make_float4(0, 0, 0, 0);
        const int slot = -r - 1;
        const int e = min((cnt_s[b] + 127) & ~127, SS);
        if (slot < e) {
            __nv_bfloat16* oh = out + ((long)b * SS + slot) * 2L * HH + c4 * 4;
            __nv_bfloat16* ol = oh + HH;
            const __nv_bfloat162 z(__nv_bfloat16(0.f), __nv_bfloat16(0.f));
            reinterpret_cast<__nv_bfloat162*>(oh)[0] = z;
            reinterpret_cast<__nv_bfloat162*>(oh)[1] = z;
            reinterpret_cast<__nv_bfloat162*>(ol)[0] = z;
            reinterpret_cast<__nv_bfloat162*>(ol)[1] = z;
        }
        return;
    }
    float4 v = reinterpret_cast<const float4*>(seq)[row * (HH / 4) + c4];
    reinterpret_cast<float4*>(cat)[row * (2 * HH / 4) + c4] = v;
    __nv_bfloat16 h0, l0, h1, l1, h2, l2, h3, l3;
    split1(v.x, h0, l0); split1(v.y, h1, l1); split1(v.z, h2, l2); split1(v.w, h3, l3);
    __nv_bfloat16* oh = out + ((long)b * SS + r) * 2L * HH + c4 * 4;
    __nv_bfloat16* ol = oh + HH;
    reinterpret_cast<__nv_bfloat162*>(oh)[0] = __nv_bfloat162(h0, h1);
    reinterpret_cast<__nv_bfloat162*>(oh)[1] = __nv_bfloat162(h2, h3);
    reinterpret_cast<__nv_bfloat162*>(ol)[0] = __nv_bfloat162(l0, l1);
    reinterpret_cast<__nv_bfloat162*>(ol)[1] = __nv_bfloat162(l2, l3);
}

// ---------------------------------------------------------------------------
// Fused tgt pass: one read of V tile -> compacted tgt2 AND compacted vT2.
// Masked t writes zeros to its pad slot in both buffers (bounded to the
// region the GEMMs read) — replaces zero_pad for tgt2 and vT2.
// ---------------------------------------------------------------------------
__global__ void tgtv_prep(const float* __restrict__ V, const int* __restrict__ rnk,
                          const int* __restrict__ cnt_t,
                          __nv_bfloat16* __restrict__ tgt2, __nv_bfloat16* __restrict__ vT2)
{
    __shared__ float tile[32][33];
    const int b = blockIdx.z;
    const int ct = cnt_t[b];
    const int eRow = min((ct + 127) & ~127, TT);   // tgt2 rows read by GEMM0
    const int eCol = min((ct + 63) & ~63, TT);     // vT2/probs cols read by GEMM5
    const int t0 = blockIdx.x * 32, h0 = blockIdx.y * 32;
    const int tx = threadIdx.x, ty = threadIdx.y;  // 32 x 8
    #pragma unroll
    for (int i = 0; i < 32; i += 8)
        tile[ty + i][tx] = V[((long)b * TT + t0 + ty + i) * HH + h0 + tx];
    __syncthreads();
    // vT2: thread (tx, ty+i) handles (h = h0+ty+i, t = t0+tx)
    #pragma unroll
    for (int i = 0; i < 32; i += 8) {
        const int h = h0 + ty + i, t = t0 + tx;
        const int j = rnk[(long)b * TT + t];
        if (j >= 0) {
            __nv_bfloat16 hh, ll;
            split1(tile[tx][ty + i], hh, ll);
            const long base = ((long)b * HH + h) * (2L * TT) + j;
            vT2[base] = hh; vT2[base + TT] = ll;
        } else {
            const int slot = -j - 1;
            if (slot < eCol) {
                const long base = ((long)b * HH + h) * (2L * TT) + slot;
                vT2[base] = __nv_bfloat16(0.f); vT2[base + TT] = __nv_bfloat16(0.f);
            }
        }
    }
    // tgt2: thread (tx, ty+i) handles (t = t0+ty+i, h = h0+tx)
    #pragma unroll
    for (int i = 0; i < 32; i += 8) {
        const int t = t0 + ty + i;
        const int j = rnk[(long)b * TT + t];
        if (j >= 0) {
            __nv_bfloat16 hh, ll;
            split1(tile[ty + i][tx], hh, ll);
            __nv_bfloat16* o = tgt2 + ((long)b * TT + j) * 2L * HH + h0 + tx;
            o[0] = hh; o[HH] = ll;
        } else {
            const int slot = -j - 1;
            if (slot < eRow) {
                __nv_bfloat16* o = tgt2 + ((long)b * TT + slot) * 2L * HH + h0 + tx;
                o[0] = __nv_bfloat16(0.f); o[HH] = __nv_bfloat16(0.f);
            }
        }
    }
}

// ---------------------------------------------------------------------------
// W: fp32 -> split bf16
// ---------------------------------------------------------------------------
__launch_bounds__(256)
__global__ void split_plain(const float* __restrict__ in, __nv_bfloat16* __restrict__ out,
                            int R, int C)
{
    const long idx = (long)blockIdx.x * blockDim.x + threadIdx.x;
    const long total = (long)R * C / 4;
    if (idx >= total) return;
    const long row = idx / (C / 4);
    const int c4 = (int)(idx % (C / 4));
    float4 v = reinterpret_cast<const float4*>(in)[idx];
    __nv_bfloat16 h0, l0, h1, l1, h2, l2, h3, l3;
    split1(v.x, h0, l0); split1(v.y, h1, l1); split1(v.z, h2, l2); split1(v.w, h3, l3);
    __nv_bfloat16* oh = out + row * 2L * C + c4 * 4;
    __nv_bfloat16* ol = oh + C;
    reinterpret_cast<__nv_bfloat162*>(oh)[0] = __nv_bfloat162(h0, h1);
    reinterpret_cast<__nv_bfloat162*>(oh)[1] = __nv_bfloat162(h2, h3);
    reinterpret_cast<__nv_bfloat162*>(ol)[0] = __nv_bfloat162(l0, l1);
    reinterpret_cast<__nv_bfloat162*>(ol)[1] = __nv_bfloat162(l2, l3);
}

// ---------------------------------------------------------------------------
// colstat: cm = (1/T) sum_all V;  vm = sum over MASKED t of V.
// ---------------------------------------------------------------------------
__launch_bounds__(256)
__global__ void colstat(const float* __restrict__ V, const int* __restrict__ tmask,
                        float* __restrict__ cm, float* __restrict__ vm)
{
    const int t = blockIdx.x * 256 + threadIdx.x;
    if (t >= BB * HH) return;
    const int b = t / HH, h = t % HH;
    const float* p = V + (long)b * TT * HH + h;
    const int* m = tmask + (long)b * TT;
    float sa = 0.f, sm_ = 0.f;
    #pragma unroll 4
    for (int i = 0; i < TT; i++) {
        const float x = p[(long)i * HH];
        sa += x;
        if (!m[i]) sm_ += x;
    }
    cm[t] = sa * (1.0f / TT);
    vm[t] = sm_;
}

// ---------------------------------------------------------------------------
// Masked seq rows: attn_out = colmean, cat second half = 0.
// ---------------------------------------------------------------------------
__launch_bounds__(256)
__global__ void fill_masked(const int* __restrict__ mask, const float* __restrict__ cm,
                            float* __restrict__ cat, float* __restrict__ attn, int writeAttn)
{
    const long t = (long)blockIdx.x * 256 + threadIdx.x;
    const long total = (long)BB * SS * (HH / 4);
    if (t >= total) return;
    const long row = t / (HH / 4);
    const int c4 = (int)(t % (HH / 4));
    if (mask[row]) return;
    const int b = (int)(row >> 12);
    float4 v = reinterpret_cast<const float4*>(cm)[(long)b * (HH / 4) + c4];
    if (writeAttn)
        reinterpret_cast<float4*>(attn)[row * (HH / 4) + c4] = v;
    reinterpret_cast<float4*>(cat)[row * (2 * HH / 4) + (HH / 4) + c4] = make_float4(0, 0, 0, 0);
}

// ---------------------------------------------------------------------------
// HMMA GEMM (split-bf16 3-term). Compaction-aware. Exactly R12's kernel.
// ---------------------------------------------------------------------------
template <int EPI>
__launch_bounds__(256)
__global__ void gemm_mma(const __nv_bfloat16* __restrict__ A,
                         const __nv_bfloat16* __restrict__ Bm,
                         long aBatch, long bBatch, int C,
                         float* __restrict__ out0, float* __restrict__ out1,
                         __nv_bfloat16* __restrict__ obf,
                         int writeAttn,
                         const __nv_bfloat16* __restrict__ A2,
                         __nv_bfloat16* __restrict__ obf2, int ySplit,
                         const int* __restrict__ cntp, const int* __restrict__ cnt2p,
                         const int* __restrict__ idxp,
                         const float* __restrict__ cvec, const float* __restrict__ vmsum)
{
    extern __shared__ char smem[];
    const uint32_t sb = smem_u32(smem);

    const int tid = threadIdx.x;
    const int wid = tid >> 5;
    const int lane = tid & 31;

    const int z = blockIdx.z;
    const long Kr = 2L * C;

    const __nv_bfloat16* Ab;
    __nv_bfloat16* obf_sel = obf;
    long orow = 0;
    int m0, cb = SS;
    if (EPI == 0) {
        if ((int)blockIdx.y < ySplit) {
            const int b = blockIdx.y >> 5;
            m0 = (blockIdx.y & 31) * 128;
            if (m0 >= cntp[b]) return;
            Ab = A + (long)b * aBatch;
            orow = (long)b * SS;
        } else {
            const int yy = (int)blockIdx.y - ySplit;
            const int b = yy >> 2;
            m0 = (yy & 3) * 128;
            if (m0 >= cnt2p[b]) return;
            Ab = A2 + (long)b * bBatch;
            orow = (long)b * TT;
            obf_sel = obf2;
        }
    } else if (EPI == 1) {
        m0 = blockIdx.y * 128;
        cb = cntp[z];
        if (m0 >= cb) return;
        if ((int)blockIdx.x * 128 >= cnt2p[z]) return;
        Ab = A + (long)z * aBatch;
    } else {
        m0 = blockIdx.y * 128;
        cb = cntp[z];
        if (m0 >= cb) return;
        Ab = A + (long)z * aBatch;
    }
    const int n0 = blockIdx.x * 128;
    const __nv_bfloat16* Bb = Bm + (long)z * ((EPI == 0) ? 0 : bBatch);

    int kc;
    if (EPI == 2) kc = (cnt2p[z] + 63) >> 6;
    else          kc = C >> 6;
    const int nk = 3 * kc;

    const int vr0 = tid >> 3;
    const int vc16 = (tid & 7) * 16;

#define LDG_STAGE(IT, S)                                                          \
    {                                                                             \
        int _it = (IT);                                                           \
        int _seg = (_it >= 2 * kc) ? 2 : ((_it >= kc) ? 1 : 0);                   \
        int _kl = _it - _seg * kc;                                                \
        long _aC = ((_seg == 1) ? C : 0) + (long)_kl * 64 + (vc16 >> 1);          \
        long _bC = ((_seg == 2) ? C : 0) + (long)_kl * 64 + (vc16 >> 1);          \
        uint32_t _sA = sb + (S) * 32768u;                                         \
        uint32_t _sB = _sA + 16384u;                                              \
        _Pragma("unroll")                                                         \
        for (int i = 0; i < 4; i++) {                                             \
            int r = vr0 + 32 * i;                                                 \
            uint32_t sw = (uint32_t)(r * 128 + (vc16 ^ ((r & 7) << 4)));          \
            cp16(_sA + sw, Ab + (long)(m0 + r) * Kr + _aC);                       \
            cp16(_sB + sw, Bb + (long)(n0 + r) * Kr + _bC);                       \
        }                                                                         \
    }

    LDG_STAGE(0, 0); CP_COMMIT();
    LDG_STAGE(1, 1); CP_COMMIT();

    const int wm = wid & 1;
    const int wn = wid >> 1;

    float acc[4][4][4] = {};

    const int arow = wm * 64 + (lane & 15);
    const int akb = (lane >> 4) * 16;
    const int brow = wn * 32 + (lane & 7) + ((lane >> 4) * 8);
    const int bkb = ((lane >> 3) & 1) * 16;

    for (int it = 0; it < nk; it++) {
        if (it + 1 < nk) cp_wait<1>(); else cp_wait<0>();
        __syncthreads();

        const uint32_t stA = sb + (uint32_t)(it % 3) * 32768u;
        const uint32_t stB = stA + 16384u;

        #pragma unroll
        for (int ks = 0; ks < 4; ks++) {
            uint32_t afr[4][4], bfr[2][4];
            #pragma unroll
            for (int mt = 0; mt < 4; mt++) {
                const int row = arow + mt * 16;
                ldsm_x4(afr[mt], stA + row * 128 + ((ks * 32 + akb) ^ ((row & 7) << 4)));
            }
            #pragma unroll
            for (int ntp = 0; ntp < 2; ntp++) {
                const int row = brow + ntp * 16;
                ldsm_x4(bfr[ntp], stB + row * 128 + ((ks * 32 + bkb) ^ ((row & 7) << 4)));
            }
            #pragma unroll
            for (int mt = 0; mt < 4; mt++)
                #pragma unroll
                for (int nt = 0; nt < 4; nt++)
                    mma_bf16(acc[mt][nt], afr[mt], &bfr[nt >> 1][(nt & 1) * 2]);
        }

        if (it + 2 < nk) { LDG_STAGE(it + 2, (it + 2) % 3); CP_COMMIT(); }
    }

    // ---- epilogue ----
    const int er = wm * 64 + (lane >> 2);
    const int ec = wn * 32 + (lane & 3) * 2;

    if (EPI == 0) {
        const int Nout = gridDim.x * 128;
        #pragma unroll
        for (int mt = 0; mt < 4; mt++)
            #pragma unroll
            for (int nt = 0; nt < 4; nt++)
                #pragma unroll
                for (int h = 0; h < 2; h++) {
                    const long row = orow + m0 + er + mt * 16 + h * 8;
                    const int col = n0 + ec + nt * 8;
                    float x0 = fmaxf(acc[mt][nt][2 * h], 0.f);
                    float x1 = fmaxf(acc[mt][nt][2 * h + 1], 0.f);
                    __nv_bfloat16 h0, l0, h1, l1;
                    split1(x0, h0, l0); split1(x1, h1, l1);
                    __nv_bfloat16* oh = obf_sel + row * 2 * Nout + col;
                    *reinterpret_cast<__nv_bfloat162*>(oh) = __nv_bfloat162(h0, h1);
                    *reinterpret_cast<__nv_bfloat162*>(oh + Nout) = __nv_bfloat162(l0, l1);
                }
    } else if (EPI == 1) {
        #pragma unroll
        for (int mt = 0; mt < 4; mt++)
            #pragma unroll
            for (int nt = 0; nt < 4; nt++)
                #pragma unroll
                for (int h = 0; h < 2; h++) {
                    const int row = m0 + er + mt * 16 + h * 8;
                    const int col = n0 + ec + nt * 8;
                    float2 v = make_float2(acc[mt][nt][2 * h], acc[mt][nt][2 * h + 1]);
                    *reinterpret_cast<float2*>(out0 + ((long)z * SS + row) * TT + col) = v;
                }
    } else {
        const long zb = (long)z * SS;
        #pragma unroll
        for (int mt = 0; mt < 4; mt++)
            #pragma unroll
            for (int h = 0; h < 2; h++) {
                const int local = m0 + er + mt * 16 + h * 8;
                if (local < cb) {
                    const float cr = cvec[zb + local];
                    const long gs = zb + idxp[zb + local];
                    #pragma unroll
                    for (int nt = 0; nt < 4; nt++) {
                        const int col = n0 + ec + nt * 8;
                        const float2 w = *reinterpret_cast<const float2*>(
                            vmsum + (long)z * HH + col);
                        float2 v = make_float2(acc[mt][nt][2 * h] + cr * w.x,
                                               acc[mt][nt][2 * h + 1] + cr * w.y);
                        if (writeAttn)
                            *reinterpret_cast<float2*>(out1 + gs * (long)HH + col) = v;
                        *reinterpret_cast<float2*>(out0 + gs * (long)(2 * HH) + HH + col) = v;
                    }
                }
            }
    }
#undef LDG_STAGE
}

// ---------------------------------------------------------------------------
// Softmax on compacted logits (R12 version).
// ---------------------------------------------------------------------------
__launch_bounds__(128)
__global__ void softmax_c(const float* __restrict__ logits, __nv_bfloat16* __restrict__ P2,
                          float* __restrict__ cvec,
                          const int* __restrict__ cnt_s, const int* __restrict__ cnt_t)
{
    const long row = blockIdx.x;
    const int b = (int)(row >> 12);
    if ((int)(row & (SS - 1)) >= cnt_s[b]) return;
    const int ct = cnt_t[b];
    const int kpad = (ct + 63) & ~63;
    const float* p = logits + row * TT;
    const int tid = threadIdx.x;
    const int warp = tid >> 5, lane = tid & 31;

    float v[4];
    #pragma unroll
    for (int i = 0; i < 4; i++) {
        const int j = tid + 128 * i;
        v[i] = (j < ct) ? p[j] : -1e30f;
    }

    float mx = fmaxf(fmaxf(v[0], v[1]), fmaxf(v[2], v[3]));
    #pragma unroll
    for (int o = 16; o > 0; o >>= 1) mx = fmaxf(mx, __shfl_xor_sync(0xffffffffu, mx, o));
    __shared__ float smx[4];
    if (lane == 0) smx[warp] = mx;
    __syncthreads();
    mx = fmaxf(fmaxf(smx[0], smx[1]), fmaxf(smx[2], smx[3]));
    if (ct < TT) mx = fmaxf(mx, 0.0f);

    float sum = 0.f;
    #pragma unroll
    for (int i = 0; i < 4; i++) {
        const int j = tid + 128 * i;
        if (j < ct) { v[i] = __expf(v[i] - mx); sum += v[i]; }
    }
    #pragma unroll
    for (int o = 16; o > 0; o >>= 1) sum += __shfl_xor_sync(0xffffffffu, sum, o);
    __shared__ float ssum[4];
    if (lane == 0) ssum[warp] = sum;
    __syncthreads();
    const float em = __expf(-mx);
    const float inv = 1.0f / (ssum[0] + ssum[1] + ssum[2] + ssum[3] + (float)(TT - ct) * em);

    if (tid == 0) cvec[row] = em * inv;

    __nv_bfloat16* out = P2 + row * 2L * TT;
    #pragma unroll
    for (int i = 0; i < 4; i++) {
        const int j = tid + 128 * i;
        if (j < ct) {
            __nv_bfloat16 h, l;
            split1(v[i] * inv, h, l);
            out[j] = h; out[TT + j] = l;
        } else if (j < kpad) {
            out[j] = __nv_bfloat16(0.f); out[TT + j] = __nv_bfloat16(0.f);
        }
    }
}

// ---------------------------------------------------------------------------

extern "C" void kernel_launch(void* const* d_in, const int* in_sizes, int n_in,
                              void* d_out, int out_size)
{
    const float* seq   = (const float*)d_in[0];
    const int*   smask = (const int*)d_in[1];
    const float* tgt   = (const float*)d_in[2];
    const int*   tmask = (const int*)d_in[3];
    const float* W     = (const float*)d_in[4];
    float* out = (float*)d_out;

    __nv_bfloat16 *p_seq2, *p_tgt2, *p_W2, *p_seqt2, *p_tgtt2, *p_probs2, *p_vT2;
    float *p_logits, *p_cm, *p_vm, *p_c;
    int *p_idx_s, *p_rnk_s, *p_cnt_s, *p_idx_t, *p_rnk_t, *p_cnt_t;
    cudaGetSymbolAddress((void**)&p_seq2, g_seq2);
    cudaGetSymbolAddress((void**)&p_tgt2, g_tgt2);
    cudaGetSymbolAddress((void**)&p_W2, g_W2);
    cudaGetSymbolAddress((void**)&p_seqt2, g_seqt2);
    cudaGetSymbolAddress((void**)&p_tgtt2, g_tgtt2);
    cudaGetSymbolAddress((void**)&p_logits, g_logits);
    cudaGetSymbolAddress((void**)&p_probs2, g_probs2);
    cudaGetSymbolAddress((void**)&p_vT2, g_vT2);
    cudaGetSymbolAddress((void**)&p_idx_s, g_idx_s);
    cudaGetSymbolAddress((void**)&p_rnk_s, g_rnk_s);
    cudaGetSymbolAddress((void**)&p_cnt_s, g_cnt_s);
    cudaGetSymbolAddress((void**)&p_idx_t, g_idx_t);
    cudaGetSymbolAddress((void**)&p_rnk_t, g_rnk_t);
    cudaGetSymbolAddress((void**)&p_cnt_t, g_cnt_t);
    cudaGetSymbolAddress((void**)&p_cm, g_cm);
    cudaGetSymbolAddress((void**)&p_vm, g_vm);
    cudaGetSymbolAddress((void**)&p_c, g_c);

    const int write_attn = (out_size >= BB * SS * 3 * HH) ? 1 : 0;
    float* out_attn = out + (size_t)BB * SS * 2 * HH;

    const int SMEM_DYN = 3 * 32768;
    cudaFuncSetAttribute(gemm_mma<0>, cudaFuncAttributeMaxDynamicSharedMemorySize, SMEM_DYN);
    cudaFuncSetAttribute(gemm_mma<1>, cudaFuncAttributeMaxDynamicSharedMemorySize, SMEM_DYN);
    cudaFuncSetAttribute(gemm_mma<2>, cudaFuncAttributeMaxDynamicSharedMemorySize, SMEM_DYN);

    const int NCHUNK_S = (BB * SS * (HH / 4) + 255) / 256;

    // 0) compaction + operand prep (pad-zeroing fused into the prep passes)
    compact_index<<<BB, 1024>>>(smask, p_idx_s, p_rnk_s, p_cnt_s, SS);
    compact_index<<<BB, 1024>>>(tmask, p_idx_t, p_rnk_t, p_cnt_t, TT);
    seq_prep<<<NCHUNK_S, 256>>>(seq, p_rnk_s, p_cnt_s, out, p_seq2);
    tgtv_prep<<<dim3(TT / 32, HH / 32, BB), dim3(32, 8)>>>(tgt, p_rnk_t, p_cnt_t,
                                                           p_tgt2, p_vT2);
    split_plain<<<(HH * HH / 4 + 255) / 256, 256>>>(W, p_W2, HH, HH);
    colstat<<<(BB * HH + 255) / 256, 256>>>(tgt, tmask, p_cm, p_vm);

    // 1+2 merged) seq_t AND tgt_t = relu(X @ W^T), both compacted
    const int Y_SEQ = (BB * SS) / 128;   // 256
    const int Y_TGT = (BB * TT) / 128;   // 32
    gemm_mma<0><<<dim3(HH / 128, Y_SEQ + Y_TGT, 1), 256, SMEM_DYN>>>(
        p_seq2, p_W2, (long)SS * 2 * HH, (long)TT * 2 * HH, HH,
        nullptr, nullptr, p_seqt2, 0,
        p_tgt2, p_tgtt2, Y_SEQ, p_cnt_s, p_cnt_t, nullptr, nullptr, nullptr);

    // 3) logits = seq_t @ tgt_t^T (rows AND cols compacted)
    gemm_mma<1><<<dim3(TT / 128, SS / 128, BB), 256, SMEM_DYN>>>(
        p_seqt2, p_tgtt2, (long)SS * 2 * HH, (long)TT * 2 * HH, HH,
        p_logits, nullptr, nullptr, 0, nullptr, nullptr, 1 << 30,
        p_cnt_s, p_cnt_t, nullptr, nullptr, nullptr);

    // 4) softmax on compacted logits; emits compacted probs + c
    softmax_c<<<BB * SS, 128>>>(p_logits, p_probs2, p_c, p_cnt_s, p_cnt_t);

    // 5) attn_out = P_compact @ V_compact + c * Vm (rank-1), scatter rows
    gemm_mma<2><<<dim3(HH / 128, SS / 128, BB), 256, SMEM_DYN>>>(
        p_probs2, p_vT2, (long)SS * 2 * TT, (long)HH * 2 * TT, TT,
        out, out_attn, nullptr, write_attn, nullptr, nullptr, 1 << 30,
        p_cnt_s, p_cnt_t, p_idx_s, p_c, p_vm);

    // 6) masked seq rows: attn = colmean(V), cat second half = 0
    fill_masked<<<NCHUNK_S, 256>>>(smask, p_cm, out, out_attn, write_attn);
}

// round 16
// speedup vs baseline: 1.1617x; 1.0411x over previous
#include <cuda_runtime.h>
#include <cuda_bf16.h>
#include <cstdint>

#define BB 8
#define SS 4096
#define TT 512
#define HH 768

// ---------------------------------------------------------------------------
// Scratch. Split bf16: [R, 2C], hi in [0,C), lo in [C,2C).
// seq/tgt buffers COMPACTED per batch; probs/vT2 compacted along t.
// rnk encoding: unmasked -> compact slot j >= 0; masked -> -(padslot)-1 where
// padslot enumerates [cnt, L) uniquely (used to zero GEMM pad rows/cols).
// ---------------------------------------------------------------------------
__device__ __align__(16) __nv_bfloat16 g_seq2 [(size_t)BB * SS * 2 * HH];
__device__ __align__(16) __nv_bfloat16 g_tgt2 [(size_t)BB * TT * 2 * HH];
__device__ __align__(16) __nv_bfloat16 g_W2   [(size_t)HH * 2 * HH];
__device__ __align__(16) __nv_bfloat16 g_seqt2[(size_t)BB * SS * 2 * HH];
__device__ __align__(16) __nv_bfloat16 g_tgtt2[(size_t)BB * TT * 2 * HH];
__device__ __align__(16) float         g_logits[(size_t)BB * SS * TT];
__device__ __align__(16) __nv_bfloat16 g_probs2[(size_t)BB * SS * 2 * TT];
__device__ __align__(16) __nv_bfloat16 g_vT2  [(size_t)BB * HH * 2 * TT];
__device__ int   g_idx_s[BB * SS];
__device__ int   g_rnk_s[BB * SS];
__device__ int   g_cnt_s[BB];
__device__ int   g_idx_t[BB * TT];
__device__ int   g_rnk_t[BB * TT];
__device__ int   g_cnt_t[BB];
__device__ float g_cm [BB * HH];    // (1/T)*sum_all_t V
__device__ float g_vm [BB * HH];    // sum_masked_t V
__device__ float g_c  [BB * SS];    // per compact seq row: masked-t prob

// ---------------------------------------------------------------------------
// Helpers
// ---------------------------------------------------------------------------
__device__ __forceinline__ uint32_t smem_u32(const void* p) {
    uint32_t a;
    asm("{ .reg .u64 t; cvta.to.shared.u64 t, %1; cvt.u32.u64 %0, t; }" : "=r"(a) : "l"(p));
    return a;
}
__device__ __forceinline__ void cp16(uint32_t saddr, const void* g) {
    asm volatile("cp.async.cg.shared.global [%0], [%1], 16;" :: "r"(saddr), "l"(g) : "memory");
}
#define CP_COMMIT() asm volatile("cp.async.commit_group;" ::: "memory")
template <int N>
__device__ __forceinline__ void cp_wait() {
    asm volatile("cp.async.wait_group %0;" :: "n"(N) : "memory");
}
__device__ __forceinline__ void ldsm_x4(uint32_t* r, uint32_t addr) {
    asm volatile("ldmatrix.sync.aligned.m8n8.x4.shared.b16 {%0,%1,%2,%3}, [%4];"
        : "=r"(r[0]), "=r"(r[1]), "=r"(r[2]), "=r"(r[3]) : "r"(addr));
}
__device__ __forceinline__ void mma_bf16(float* c, const uint32_t* a, const uint32_t* b) {
    asm volatile(
        "mma.sync.aligned.m16n8k16.row.col.f32.bf16.bf16.f32 "
        "{%0,%1,%2,%3}, {%4,%5,%6,%7}, {%8,%9}, {%0,%1,%2,%3};"
        : "+f"(c[0]), "+f"(c[1]), "+f"(c[2]), "+f"(c[3])
        : "r"(a[0]), "r"(a[1]), "r"(a[2]), "r"(a[3]), "r"(b[0]), "r"(b[1]));
}
__device__ __forceinline__ void split1(float x, __nv_bfloat16& h, __nv_bfloat16& l) {
    h = __float2bfloat16(x);
    l = __float2bfloat16(x - __bfloat162float(h));
}

// ---------------------------------------------------------------------------
// Per-batch ordered compaction: idx (compact->orig), cnt, and rnk with the
// masked-pad-slot encoding described above.
// ---------------------------------------------------------------------------
__global__ void compact_index(const int* __restrict__ mask, int* __restrict__ idx,
                              int* __restrict__ rnk, int* __restrict__ cnt, int L)
{
    const int b = blockIdx.x;
    const int tid = threadIdx.x;
    const int lane = tid & 31, w = tid >> 5;
    const int* m = mask + (long)b * L;

    int v[4], c = 0;
    #pragma unroll
    for (int i = 0; i < 4; i++) {
        const int p = tid * 4 + i;
        v[i] = (p < L) ? m[p] : 0;
        c += v[i];
    }
    int sc = c;
    #pragma unroll
    for (int o = 1; o < 32; o <<= 1) {
        int t = __shfl_up_sync(0xffffffffu, sc, o);
        if (lane >= o) sc += t;
    }
    __shared__ int ws[32];
    if (lane == 31) ws[w] = sc;
    __syncthreads();
    if (w == 0) {
        int t = ws[lane];
        #pragma unroll
        for (int o = 1; o < 32; o <<= 1) {
            int u = __shfl_up_sync(0xffffffffu, t, o);
            if (lane >= o) t += u;
        }
        ws[lane] = t;
    }
    __syncthreads();
    int base = sc - c + (w ? ws[w - 1] : 0);   // unmasked before p
    const int total = ws[31];
    #pragma unroll
    for (int i = 0; i < 4; i++) {
        const int p = tid * 4 + i;
        if (p < L) {
            if (v[i]) { idx[(long)b * L + base] = p; rnk[(long)b * L + p] = base; base++; }
            else {
                rnk[(long)b * L + p] = -(total + (p - base)) - 1;
            }
        }
    }
    if (tid == 0) cnt[b] = total;
}

// ---------------------------------------------------------------------------
// Fused seq pass: cat first half + compacted split seq2; masked rows zero
// their pad slot (within the ceil128 GEMM-read region).
// ---------------------------------------------------------------------------
__launch_bounds__(256)
__global__ void seq_prep(const float* __restrict__ seq, const int* __restrict__ rnk,
                         const int* __restrict__ cnt_s,
                         float* __restrict__ cat, __nv_bfloat16* __restrict__ out)
{
    const long t = (long)blockIdx.x * 256 + threadIdx.x;
    const long total = (long)BB * SS * (HH / 4);
    if (t >= total) return;
    const long row = t / (HH / 4);
    const int c4 = (int)(t % (HH / 4));
    const int b = (int)(row >> 12);
    const int r = rnk[row];
    if (r < 0) {
        reinterpret_cast<float4*>(cat)[row * (2 * HH / 4) + c4] = make_float4(0, 0, 0, 0);
        const int slot = -r - 1;
        const int e = min((cnt_s[b] + 127) & ~127, SS);
        if (slot < e) {
            __nv_bfloat16* oh = out + ((long)b * SS + slot) * 2L * HH + c4 * 4;
            __nv_bfloat16* ol = oh + HH;
            const __nv_bfloat162 z(__nv_bfloat16(0.f), __nv_bfloat16(0.f));
            reinterpret_cast<__nv_bfloat162*>(oh)[0] = z;
            reinterpret_cast<__nv_bfloat162*>(oh)[1] = z;
            reinterpret_cast<__nv_bfloat162*>(ol)[0] = z;
            reinterpret_cast<__nv_bfloat162*>(ol)[1] = z;
        }
        return;
    }
    float4 v = reinterpret_cast<const float4*>(seq)[row * (HH / 4) + c4];
    reinterpret_cast<float4*>(cat)[row * (2 * HH / 4) + c4] = v;
    __nv_bfloat16 h0, l0, h1, l1, h2, l2, h3, l3;
    split1(v.x, h0, l0); split1(v.y, h1, l1); split1(v.z, h2, l2); split1(v.w, h3, l3);
    __nv_bfloat16* oh = out + ((long)b * SS + r) * 2L * HH + c4 * 4;
    __nv_bfloat16* ol = oh + HH;
    reinterpret_cast<__nv_bfloat162*>(oh)[0] = __nv_bfloat162(h0, h1);
    reinterpret_cast<__nv_bfloat162*>(oh)[1] = __nv_bfloat162(h2, h3);
    reinterpret_cast<__nv_bfloat162*>(ol)[0] = __nv_bfloat162(l0, l1);
    reinterpret_cast<__nv_bfloat162*>(ol)[1] = __nv_bfloat162(l2, l3);
}

// ---------------------------------------------------------------------------
// Fused tgt pass: compacted tgt2 AND compacted vT2; masked t zeroes its pad
// slot in both buffers (bounded to the GEMM-read regions).
// ---------------------------------------------------------------------------
__global__ void tgtv_prep(const float* __restrict__ V, const int* __restrict__ rnk,
                          const int* __restrict__ cnt_t,
                          __nv_bfloat16* __restrict__ tgt2, __nv_bfloat16* __restrict__ vT2)
{
    __shared__ float tile[32][33];
    const int b = blockIdx.z;
    const int ct = cnt_t[b];
    const int eRow = min((ct + 127) & ~127, TT);
    const int eCol = min((ct + 63) & ~63, TT);
    const int t0 = blockIdx.x * 32, h0 = blockIdx.y * 32;
    const int tx = threadIdx.x, ty = threadIdx.y;  // 32 x 8
    #pragma unroll
    for (int i = 0; i < 32; i += 8)
        tile[ty + i][tx] = V[((long)b * TT + t0 + ty + i) * HH + h0 + tx];
    __syncthreads();
    #pragma unroll
    for (int i = 0; i < 32; i += 8) {
        const int h = h0 + ty + i, t = t0 + tx;
        const int j = rnk[(long)b * TT + t];
        if (j >= 0) {
            __nv_bfloat16 hh, ll;
            split1(tile[tx][ty + i], hh, ll);
            const long base = ((long)b * HH + h) * (2L * TT) + j;
            vT2[base] = hh; vT2[base + TT] = ll;
        } else {
            const int slot = -j - 1;
            if (slot < eCol) {
                const long base = ((long)b * HH + h) * (2L * TT) + slot;
                vT2[base] = __nv_bfloat16(0.f); vT2[base + TT] = __nv_bfloat16(0.f);
            }
        }
    }
    #pragma unroll
    for (int i = 0; i < 32; i += 8) {
        const int t = t0 + ty + i;
        const int j = rnk[(long)b * TT + t];
        if (j >= 0) {
            __nv_bfloat16 hh, ll;
            split1(tile[ty + i][tx], hh, ll);
            __nv_bfloat16* o = tgt2 + ((long)b * TT + j) * 2L * HH + h0 + tx;
            o[0] = hh; o[HH] = ll;
        } else {
            const int slot = -j - 1;
            if (slot < eRow) {
                __nv_bfloat16* o = tgt2 + ((long)b * TT + slot) * 2L * HH + h0 + tx;
                o[0] = __nv_bfloat16(0.f); o[HH] = __nv_bfloat16(0.f);
            }
        }
    }
}

// ---------------------------------------------------------------------------
// W: fp32 -> split bf16
// ---------------------------------------------------------------------------
__launch_bounds__(256)
__global__ void split_plain(const float* __restrict__ in, __nv_bfloat16* __restrict__ out,
                            int R, int C)
{
    const long idx = (long)blockIdx.x * blockDim.x + threadIdx.x;
    const long total = (long)R * C / 4;
    if (idx >= total) return;
    const long row = idx / (C / 4);
    const int c4 = (int)(idx % (C / 4));
    float4 v = reinterpret_cast<const float4*>(in)[idx];
    __nv_bfloat16 h0, l0, h1, l1, h2, l2, h3, l3;
    split1(v.x, h0, l0); split1(v.y, h1, l1); split1(v.z, h2, l2); split1(v.w, h3, l3);
    __nv_bfloat16* oh = out + row * 2L * C + c4 * 4;
    __nv_bfloat16* ol = oh + C;
    reinterpret_cast<__nv_bfloat162*>(oh)[0] = __nv_bfloat162(h0, h1);
    reinterpret_cast<__nv_bfloat162*>(oh)[1] = __nv_bfloat162(h2, h3);
    reinterpret_cast<__nv_bfloat162*>(ol)[0] = __nv_bfloat162(l0, l1);
    reinterpret_cast<__nv_bfloat162*>(ol)[1] = __nv_bfloat162(l2, l3);
}

// ---------------------------------------------------------------------------
// colstat: cm = (1/T) sum_all V;  vm = sum over MASKED t of V.
// ---------------------------------------------------------------------------
__launch_bounds__(256)
__global__ void colstat(const float* __restrict__ V, const int* __restrict__ tmask,
                        float* __restrict__ cm, float* __restrict__ vm)
{
    const int t = blockIdx.x * 256 + threadIdx.x;
    if (t >= BB * HH) return;
    const int b = t / HH, h = t % HH;
    const float* p = V + (long)b * TT * HH + h;
    const int* m = tmask + (long)b * TT;
    float sa = 0.f, sm_ = 0.f;
    #pragma unroll 4
    for (int i = 0; i < TT; i++) {
        const float x = p[(long)i * HH];
        sa += x;
        if (!m[i]) sm_ += x;
    }
    cm[t] = sa * (1.0f / TT);
    vm[t] = sm_;
}

// ---------------------------------------------------------------------------
// Masked seq rows: attn_out = colmean, cat second half = 0.
// (Writes only masked rows — disjoint from GEMM5's unmasked-row scatter and
//  from seq_prep's cat-first-half writes, so it can run concurrently.)
// ---------------------------------------------------------------------------
__launch_bounds__(256)
__global__ void fill_masked(const int* __restrict__ mask, const float* __restrict__ cm,
                            float* __restrict__ cat, float* __restrict__ attn, int writeAttn)
{
    const long t = (long)blockIdx.x * 256 + threadIdx.x;
    const long total = (long)BB * SS * (HH / 4);
    if (t >= total) return;
    const long row = t / (HH / 4);
    const int c4 = (int)(t % (HH / 4));
    if (mask[row]) return;
    const int b = (int)(row >> 12);
    float4 v = reinterpret_cast<const float4*>(cm)[(long)b * (HH / 4) + c4];
    if (writeAttn)
        reinterpret_cast<float4*>(attn)[row * (HH / 4) + c4] = v;
    reinterpret_cast<float4*>(cat)[row * (2 * HH / 4) + (HH / 4) + c4] = make_float4(0, 0, 0, 0);
}

// ---------------------------------------------------------------------------
// HMMA GEMM (split-bf16 3-term). Compaction-aware. Exactly R12's kernel.
// ---------------------------------------------------------------------------
template <int EPI>
__launch_bounds__(256)
__global__ void gemm_mma(const __nv_bfloat16* __restrict__ A,
                         const __nv_bfloat16* __restrict__ Bm,
                         long aBatch, long bBatch, int C,
                         float* __restrict__ out0, float* __restrict__ out1,
                         __nv_bfloat16* __restrict__ obf,
                         int writeAttn,
                         const __nv_bfloat16* __restrict__ A2,
                         __nv_bfloat16* __restrict__ obf2, int ySplit,
                         const int* __restrict__ cntp, const int* __restrict__ cnt2p,
                         const int* __restrict__ idxp,
                         const float* __restrict__ cvec, const float* __restrict__ vmsum)
{
    extern __shared__ char smem[];
    const uint32_t sb = smem_u32(smem);

    const int tid = threadIdx.x;
    const int wid = tid >> 5;
    const int lane = tid & 31;

    const int z = blockIdx.z;
    const long Kr = 2L * C;

    const __nv_bfloat16* Ab;
    __nv_bfloat16* obf_sel = obf;
    long orow = 0;
    int m0, cb = SS;
    if (EPI == 0) {
        if ((int)blockIdx.y < ySplit) {
            const int b = blockIdx.y >> 5;
            m0 = (blockIdx.y & 31) * 128;
            if (m0 >= cntp[b]) return;
            Ab = A + (long)b * aBatch;
            orow = (long)b * SS;
        } else {
            const int yy = (int)blockIdx.y - ySplit;
            const int b = yy >> 2;
            m0 = (yy & 3) * 128;
            if (m0 >= cnt2p[b]) return;
            Ab = A2 + (long)b * bBatch;
            orow = (long)b * TT;
            obf_sel = obf2;
        }
    } else if (EPI == 1) {
        m0 = blockIdx.y * 128;
        cb = cntp[z];
        if (m0 >= cb) return;
        if ((int)blockIdx.x * 128 >= cnt2p[z]) return;
        Ab = A + (long)z * aBatch;
    } else {
        m0 = blockIdx.y * 128;
        cb = cntp[z];
        if (m0 >= cb) return;
        Ab = A + (long)z * aBatch;
    }
    const int n0 = blockIdx.x * 128;
    const __nv_bfloat16* Bb = Bm + (long)z * ((EPI == 0) ? 0 : bBatch);

    int kc;
    if (EPI == 2) kc = (cnt2p[z] + 63) >> 6;
    else          kc = C >> 6;
    const int nk = 3 * kc;

    const int vr0 = tid >> 3;
    const int vc16 = (tid & 7) * 16;

#define LDG_STAGE(IT, S)                                                          \
    {                                                                             \
        int _it = (IT);                                                           \
        int _seg = (_it >= 2 * kc) ? 2 : ((_it >= kc) ? 1 : 0);                   \
        int _kl = _it - _seg * kc;                                                \
        long _aC = ((_seg == 1) ? C : 0) + (long)_kl * 64 + (vc16 >> 1);          \
        long _bC = ((_seg == 2) ? C : 0) + (long)_kl * 64 + (vc16 >> 1);          \
        uint32_t _sA = sb + (S) * 32768u;                                         \
        uint32_t _sB = _sA + 16384u;                                              \
        _Pragma("unroll")                                                         \
        for (int i = 0; i < 4; i++) {                                             \
            int r = vr0 + 32 * i;                                                 \
            uint32_t sw = (uint32_t)(r * 128 + (vc16 ^ ((r & 7) << 4)));          \
            cp16(_sA + sw, Ab + (long)(m0 + r) * Kr + _aC);                       \
            cp16(_sB + sw, Bb + (long)(n0 + r) * Kr + _bC);                       \
        }                                                                         \
    }

    LDG_STAGE(0, 0); CP_COMMIT();
    LDG_STAGE(1, 1); CP_COMMIT();

    const int wm = wid & 1;
    const int wn = wid >> 1;

    float acc[4][4][4] = {};

    const int arow = wm * 64 + (lane & 15);
    const int akb = (lane >> 4) * 16;
    const int brow = wn * 32 + (lane & 7) + ((lane >> 4) * 8);
    const int bkb = ((lane >> 3) & 1) * 16;

    for (int it = 0; it < nk; it++) {
        if (it + 1 < nk) cp_wait<1>(); else cp_wait<0>();
        __syncthreads();

        const uint32_t stA = sb + (uint32_t)(it % 3) * 32768u;
        const uint32_t stB = stA + 16384u;

        #pragma unroll
        for (int ks = 0; ks < 4; ks++) {
            uint32_t afr[4][4], bfr[2][4];
            #pragma unroll
            for (int mt = 0; mt < 4; mt++) {
                const int row = arow + mt * 16;
                ldsm_x4(afr[mt], stA + row * 128 + ((ks * 32 + akb) ^ ((row & 7) << 4)));
            }
            #pragma unroll
            for (int ntp = 0; ntp < 2; ntp++) {
                const int row = brow + ntp * 16;
                ldsm_x4(bfr[ntp], stB + row * 128 + ((ks * 32 + bkb) ^ ((row & 7) << 4)));
            }
            #pragma unroll
            for (int mt = 0; mt < 4; mt++)
                #pragma unroll
                for (int nt = 0; nt < 4; nt++)
                    mma_bf16(acc[mt][nt], afr[mt], &bfr[nt >> 1][(nt & 1) * 2]);
        }

        if (it + 2 < nk) { LDG_STAGE(it + 2, (it + 2) % 3); CP_COMMIT(); }
    }

    // ---- epilogue ----
    const int er = wm * 64 + (lane >> 2);
    const int ec = wn * 32 + (lane & 3) * 2;

    if (EPI == 0) {
        const int Nout = gridDim.x * 128;
        #pragma unroll
        for (int mt = 0; mt < 4; mt++)
            #pragma unroll
            for (int nt = 0; nt < 4; nt++)
                #pragma unroll
                for (int h = 0; h < 2; h++) {
                    const long row = orow + m0 + er + mt * 16 + h * 8;
                    const int col = n0 + ec + nt * 8;
                    float x0 = fmaxf(acc[mt][nt][2 * h], 0.f);
                    float x1 = fmaxf(acc[mt][nt][2 * h + 1], 0.f);
                    __nv_bfloat16 h0, l0, h1, l1;
                    split1(x0, h0, l0); split1(x1, h1, l1);
                    __nv_bfloat16* oh = obf_sel + row * 2 * Nout + col;
                    *reinterpret_cast<__nv_bfloat162*>(oh) = __nv_bfloat162(h0, h1);
                    *reinterpret_cast<__nv_bfloat162*>(oh + Nout) = __nv_bfloat162(l0, l1);
                }
    } else if (EPI == 1) {
        #pragma unroll
        for (int mt = 0; mt < 4; mt++)
            #pragma unroll
            for (int nt = 0; nt < 4; nt++)
                #pragma unroll
                for (int h = 0; h < 2; h++) {
                    const int row = m0 + er + mt * 16 + h * 8;
                    const int col = n0 + ec + nt * 8;
                    float2 v = make_float2(acc[mt][nt][2 * h], acc[mt][nt][2 * h + 1]);
                    *reinterpret_cast<float2*>(out0 + ((long)z * SS + row) * TT + col) = v;
                }
    } else {
        const long zb = (long)z * SS;
        #pragma unroll
        for (int mt = 0; mt < 4; mt++)
            #pragma unroll
            for (int h = 0; h < 2; h++) {
                const int local = m0 + er + mt * 16 + h * 8;
                if (local < cb) {
                    const float cr = cvec[zb + local];
                    const long gs = zb + idxp[zb + local];
                    #pragma unroll
                    for (int nt = 0; nt < 4; nt++) {
                        const int col = n0 + ec + nt * 8;
                        const float2 w = *reinterpret_cast<const float2*>(
                            vmsum + (long)z * HH + col);
                        float2 v = make_float2(acc[mt][nt][2 * h] + cr * w.x,
                                               acc[mt][nt][2 * h + 1] + cr * w.y);
                        if (writeAttn)
                            *reinterpret_cast<float2*>(out1 + gs * (long)HH + col) = v;
                        *reinterpret_cast<float2*>(out0 + gs * (long)(2 * HH) + HH + col) = v;
                    }
                }
            }
    }
#undef LDG_STAGE
}

// ---------------------------------------------------------------------------
// Softmax on compacted logits (R12 version).
// ---------------------------------------------------------------------------
__launch_bounds__(128)
__global__ void softmax_c(const float* __restrict__ logits, __nv_bfloat16* __restrict__ P2,
                          float* __restrict__ cvec,
                          const int* __restrict__ cnt_s, const int* __restrict__ cnt_t)
{
    const long row = blockIdx.x;
    const int b = (int)(row >> 12);
    if ((int)(row & (SS - 1)) >= cnt_s[b]) return;
    const int ct = cnt_t[b];
    const int kpad = (ct + 63) & ~63;
    const float* p = logits + row * TT;
    const int tid = threadIdx.x;
    const int warp = tid >> 5, lane = tid & 31;

    float v[4];
    #pragma unroll
    for (int i = 0; i < 4; i++) {
        const int j = tid + 128 * i;
        v[i] = (j < ct) ? p[j] : -1e30f;
    }

    float mx = fmaxf(fmaxf(v[0], v[1]), fmaxf(v[2], v[3]));
    #pragma unroll
    for (int o = 16; o > 0; o >>= 1) mx = fmaxf(mx, __shfl_xor_sync(0xffffffffu, mx, o));
    __shared__ float smx[4];
    if (lane == 0) smx[warp] = mx;
    __syncthreads();
    mx = fmaxf(fmaxf(smx[0], smx[1]), fmaxf(smx[2], smx[3]));
    if (ct < TT) mx = fmaxf(mx, 0.0f);

    float sum = 0.f;
    #pragma unroll
    for (int i = 0; i < 4; i++) {
        const int j = tid + 128 * i;
        if (j < ct) { v[i] = __expf(v[i] - mx); sum += v[i]; }
    }
    #pragma unroll
    for (int o = 16; o > 0; o >>= 1) sum += __shfl_xor_sync(0xffffffffu, sum, o);
    __shared__ float ssum[4];
    if (lane == 0) ssum[warp] = sum;
    __syncthreads();
    const float em = __expf(-mx);
    const float inv = 1.0f / (ssum[0] + ssum[1] + ssum[2] + ssum[3] + (float)(TT - ct) * em);

    if (tid == 0) cvec[row] = em * inv;

    __nv_bfloat16* out = P2 + row * 2L * TT;
    #pragma unroll
    for (int i = 0; i < 4; i++) {
        const int j = tid + 128 * i;
        if (j < ct) {
            __nv_bfloat16 h, l;
            split1(v[i] * inv, h, l);
            out[j] = h; out[TT + j] = l;
        } else if (j < kpad) {
            out[j] = __nv_bfloat16(0.f); out[TT + j] = __nv_bfloat16(0.f);
        }
    }
}

// ---------------------------------------------------------------------------
// One-time side streams/events for graph forking (created on the first,
// uncaptured correctness call; reused identically in the captured call).
// ---------------------------------------------------------------------------
static cudaStream_t g_s1 = nullptr, g_s2 = nullptr;
static cudaEvent_t g_e0 = nullptr, g_e1 = nullptr, g_e2a = nullptr, g_e2b = nullptr;

extern "C" void kernel_launch(void* const* d_in, const int* in_sizes, int n_in,
                              void* d_out, int out_size)
{
    const float* seq   = (const float*)d_in[0];
    const int*   smask = (const int*)d_in[1];
    const float* tgt   = (const float*)d_in[2];
    const int*   tmask = (const int*)d_in[3];
    const float* W     = (const float*)d_in[4];
    float* out = (float*)d_out;

    if (!g_s1) {
        cudaStreamCreateWithFlags(&g_s1, cudaStreamNonBlocking);
        cudaStreamCreateWithFlags(&g_s2, cudaStreamNonBlocking);
        cudaEventCreateWithFlags(&g_e0, cudaEventDisableTiming);
        cudaEventCreateWithFlags(&g_e1, cudaEventDisableTiming);
        cudaEventCreateWithFlags(&g_e2a, cudaEventDisableTiming);
        cudaEventCreateWithFlags(&g_e2b, cudaEventDisableTiming);
    }

    __nv_bfloat16 *p_seq2, *p_tgt2, *p_W2, *p_seqt2, *p_tgtt2, *p_probs2, *p_vT2;
    float *p_logits, *p_cm, *p_vm, *p_c;
    int *p_idx_s, *p_rnk_s, *p_cnt_s, *p_idx_t, *p_rnk_t, *p_cnt_t;
    cudaGetSymbolAddress((void**)&p_seq2, g_seq2);
    cudaGetSymbolAddress((void**)&p_tgt2, g_tgt2);
    cudaGetSymbolAddress((void**)&p_W2, g_W2);
    cudaGetSymbolAddress((void**)&p_seqt2, g_seqt2);
    cudaGetSymbolAddress((void**)&p_tgtt2, g_tgtt2);
    cudaGetSymbolAddress((void**)&p_logits, g_logits);
    cudaGetSymbolAddress((void**)&p_probs2, g_probs2);
    cudaGetSymbolAddress((void**)&p_vT2, g_vT2);
    cudaGetSymbolAddress((void**)&p_idx_s, g_idx_s);
    cudaGetSymbolAddress((void**)&p_rnk_s, g_rnk_s);
    cudaGetSymbolAddress((void**)&p_cnt_s, g_cnt_s);
    cudaGetSymbolAddress((void**)&p_idx_t, g_idx_t);
    cudaGetSymbolAddress((void**)&p_rnk_t, g_rnk_t);
    cudaGetSymbolAddress((void**)&p_cnt_t, g_cnt_t);
    cudaGetSymbolAddress((void**)&p_cm, g_cm);
    cudaGetSymbolAddress((void**)&p_vm, g_vm);
    cudaGetSymbolAddress((void**)&p_c, g_c);

    const int write_attn = (out_size >= BB * SS * 3 * HH) ? 1 : 0;
    float* out_attn = out + (size_t)BB * SS * 2 * HH;

    const int SMEM_DYN = 3 * 32768;
    cudaFuncSetAttribute(gemm_mma<0>, cudaFuncAttributeMaxDynamicSharedMemorySize, SMEM_DYN);
    cudaFuncSetAttribute(gemm_mma<1>, cudaFuncAttributeMaxDynamicSharedMemorySize, SMEM_DYN);
    cudaFuncSetAttribute(gemm_mma<2>, cudaFuncAttributeMaxDynamicSharedMemorySize, SMEM_DYN);

    const int NCHUNK_S = (BB * SS * (HH / 4) + 255) / 256;

    // ---- fork: attach side streams to the capture origin ----
    cudaEventRecord(g_e0, 0);
    cudaStreamWaitEvent(g_s1, g_e0, 0);
    cudaStreamWaitEvent(g_s2, g_e0, 0);

    // stream0 (long pole): seq compaction + seq prep
    compact_index<<<BB, 1024>>>(smask, p_idx_s, p_rnk_s, p_cnt_s, SS);
    seq_prep<<<NCHUNK_S, 256>>>(seq, p_rnk_s, p_cnt_s, out, p_seq2);

    // s1: tgt compaction + tgt/vT prep
    compact_index<<<BB, 1024, 0, g_s1>>>(tmask, p_idx_t, p_rnk_t, p_cnt_t, TT);
    tgtv_prep<<<dim3(TT / 32, HH / 32, BB), dim3(32, 8), 0, g_s1>>>(
        tgt, p_rnk_t, p_cnt_t, p_tgt2, p_vT2);
    cudaEventRecord(g_e1, g_s1);

    // s2: W split + colstat, then fill_masked (overlaps the GEMMs; its writes
    // are disjoint from GEMM5's unmasked-row scatter and seq_prep's writes)
    split_plain<<<(HH * HH / 4 + 255) / 256, 256, 0, g_s2>>>(W, p_W2, HH, HH);
    colstat<<<(BB * HH + 255) / 256, 256, 0, g_s2>>>(tgt, tmask, p_cm, p_vm);
    cudaEventRecord(g_e2a, g_s2);
    fill_masked<<<NCHUNK_S, 256, 0, g_s2>>>(smask, p_cm, out, out_attn, write_attn);
    cudaEventRecord(g_e2b, g_s2);

    // join prep results needed by the GEMM chain
    cudaStreamWaitEvent(0, g_e1, 0);
    cudaStreamWaitEvent(0, g_e2a, 0);

    // 1+2 merged) seq_t AND tgt_t = relu(X @ W^T), both compacted
    const int Y_SEQ = (BB * SS) / 128;   // 256
    const int Y_TGT = (BB * TT) / 128;   // 32
    gemm_mma<0><<<dim3(HH / 128, Y_SEQ + Y_TGT, 1), 256, SMEM_DYN>>>(
        p_seq2, p_W2, (long)SS * 2 * HH, (long)TT * 2 * HH, HH,
        nullptr, nullptr, p_seqt2, 0,
        p_tgt2, p_tgtt2, Y_SEQ, p_cnt_s, p_cnt_t, nullptr, nullptr, nullptr);

    // 3) logits = seq_t @ tgt_t^T (rows AND cols compacted)
    gemm_mma<1><<<dim3(TT / 128, SS / 128, BB), 256, SMEM_DYN>>>(
        p_seqt2, p_tgtt2, (long)SS * 2 * HH, (long)TT * 2 * HH, HH,
        p_logits, nullptr, nullptr, 0, nullptr, nullptr, 1 << 30,
        p_cnt_s, p_cnt_t, nullptr, nullptr, nullptr);

    // 4) softmax on compacted logits; emits compacted probs + c
    softmax_c<<<BB * SS, 128>>>(p_logits, p_probs2, p_c, p_cnt_s, p_cnt_t);

    // 5) attn_out = P_compact @ V_compact + c * Vm (rank-1), scatter rows
    gemm_mma<2><<<dim3(HH / 128, SS / 128, BB), 256, SMEM_DYN>>>(
        p_probs2, p_vT2, (long)SS * 2 * TT, (long)HH * 2 * TT, TT,
        out, out_attn, nullptr, write_attn, nullptr, nullptr, 1 << 30,
        p_cnt_s, p_cnt_t, p_idx_s, p_c, p_vm);

    // join fill_masked before graph end
    cudaStreamWaitEvent(0, g_e2b, 0);
}

// round 17
// speedup vs baseline: 1.2188x; 1.0491x over previous
#include <cuda_runtime.h>
#include <cuda_bf16.h>
#include <cstdint>

#define BB 8
#define SS 4096
#define TT 512
#define HH 768

// ---------------------------------------------------------------------------
// Scratch. Split bf16: [R, 2C], hi in [0,C), lo in [C,2C).
// seq/tgt buffers COMPACTED per batch; probs/vT2 compacted along t.
// rnk encoding: unmasked -> compact slot j >= 0; masked -> -(padslot)-1.
// ---------------------------------------------------------------------------
__device__ __align__(16) __nv_bfloat16 g_seq2 [(size_t)BB * SS * 2 * HH];
__device__ __align__(16) __nv_bfloat16 g_tgt2 [(size_t)BB * TT * 2 * HH];
__device__ __align__(16) __nv_bfloat16 g_W2   [(size_t)HH * 2 * HH];
__device__ __align__(16) __nv_bfloat16 g_seqt2[(size_t)BB * SS * 2 * HH];
__device__ __align__(16) __nv_bfloat16 g_tgtt2[(size_t)BB * TT * 2 * HH];
__device__ __align__(16) float         g_logits[(size_t)BB * SS * TT];
__device__ __align__(16) __nv_bfloat16 g_probs2[(size_t)BB * SS * 2 * TT];
__device__ __align__(16) __nv_bfloat16 g_vT2  [(size_t)BB * HH * 2 * TT];
__device__ int   g_idx_s[BB * SS];
__device__ int   g_rnk_s[BB * SS];
__device__ int   g_cnt_s[BB];
__device__ int   g_idx_t[BB * TT];
__device__ int   g_rnk_t[BB * TT];
__device__ int   g_cnt_t[BB];
__device__ float g_cm [BB * HH];    // (1/T)*sum_all_t V
__device__ float g_vm [BB * HH];    // sum_masked_t V
__device__ float g_c  [BB * SS];    // per compact seq row: masked-t prob

// ---------------------------------------------------------------------------
// Helpers
// ---------------------------------------------------------------------------
__device__ __forceinline__ uint32_t smem_u32(const void* p) {
    uint32_t a;
    asm("{ .reg .u64 t; cvta.to.shared.u64 t, %1; cvt.u32.u64 %0, t; }" : "=r"(a) : "l"(p));
    return a;
}
__device__ __forceinline__ void cp16(uint32_t saddr, const void* g) {
    asm volatile("cp.async.cg.shared.global [%0], [%1], 16;" :: "r"(saddr), "l"(g) : "memory");
}
#define CP_COMMIT() asm volatile("cp.async.commit_group;" ::: "memory")
template <int N>
__device__ __forceinline__ void cp_wait() {
    asm volatile("cp.async.wait_group %0;" :: "n"(N) : "memory");
}
__device__ __forceinline__ void ldsm_x4(uint32_t* r, uint32_t addr) {
    asm volatile("ldmatrix.sync.aligned.m8n8.x4.shared.b16 {%0,%1,%2,%3}, [%4];"
        : "=r"(r[0]), "=r"(r[1]), "=r"(r[2]), "=r"(r[3]) : "r"(addr));
}
__device__ __forceinline__ void mma_bf16(float* c, const uint32_t* a, const uint32_t* b) {
    asm volatile(
        "mma.sync.aligned.m16n8k16.row.col.f32.bf16.bf16.f32 "
        "{%0,%1,%2,%3}, {%4,%5,%6,%7}, {%8,%9}, {%0,%1,%2,%3};"
        : "+f"(c[0]), "+f"(c[1]), "+f"(c[2]), "+f"(c[3])
        : "r"(a[0]), "r"(a[1]), "r"(a[2]), "r"(a[3]), "r"(b[0]), "r"(b[1]));
}
__device__ __forceinline__ void split1(float x, __nv_bfloat16& h, __nv_bfloat16& l) {
    h = __float2bfloat16(x);
    l = __float2bfloat16(x - __bfloat162float(h));
}

// ---------------------------------------------------------------------------
// Per-batch ordered compaction with masked-pad-slot rnk encoding.
// ---------------------------------------------------------------------------
__global__ void compact_index(const int* __restrict__ mask, int* __restrict__ idx,
                              int* __restrict__ rnk, int* __restrict__ cnt, int L)
{
    const int b = blockIdx.x;
    const int tid = threadIdx.x;
    const int lane = tid & 31, w = tid >> 5;
    const int* m = mask + (long)b * L;

    int v[4], c = 0;
    #pragma unroll
    for (int i = 0; i < 4; i++) {
        const int p = tid * 4 + i;
        v[i] = (p < L) ? m[p] : 0;
        c += v[i];
    }
    int sc = c;
    #pragma unroll
    for (int o = 1; o < 32; o <<= 1) {
        int t = __shfl_up_sync(0xffffffffu, sc, o);
        if (lane >= o) sc += t;
    }
    __shared__ int ws[32];
    if (lane == 31) ws[w] = sc;
    __syncthreads();
    if (w == 0) {
        int t = ws[lane];
        #pragma unroll
        for (int o = 1; o < 32; o <<= 1) {
            int u = __shfl_up_sync(0xffffffffu, t, o);
            if (lane >= o) t += u;
        }
        ws[lane] = t;
    }
    __syncthreads();
    int base = sc - c + (w ? ws[w - 1] : 0);
    const int total = ws[31];
    #pragma unroll
    for (int i = 0; i < 4; i++) {
        const int p = tid * 4 + i;
        if (p < L) {
            if (v[i]) { idx[(long)b * L + base] = p; rnk[(long)b * L + p] = base; base++; }
            else {
                rnk[(long)b * L + p] = -(total + (p - base)) - 1;
            }
        }
    }
    if (tid == 0) cnt[b] = total;
}

// ---------------------------------------------------------------------------
// Critical-path seq pass (slimmed): compacted split seq2 only; masked rows
// zero their pad slot. NO cat writes (moved to cat_fill on the side stream).
// ---------------------------------------------------------------------------
__launch_bounds__(256)
__global__ void seq_prep(const float* __restrict__ seq, const int* __restrict__ rnk,
                         const int* __restrict__ cnt_s, __nv_bfloat16* __restrict__ out)
{
    const long t = (long)blockIdx.x * 256 + threadIdx.x;
    const long total = (long)BB * SS * (HH / 4);
    if (t >= total) return;
    const long row = t / (HH / 4);
    const int c4 = (int)(t % (HH / 4));
    const int b = (int)(row >> 12);
    const int r = rnk[row];
    if (r < 0) {
        const int slot = -r - 1;
        const int e = min((cnt_s[b] + 127) & ~127, SS);
        if (slot < e) {
            __nv_bfloat16* oh = out + ((long)b * SS + slot) * 2L * HH + c4 * 4;
            __nv_bfloat16* ol = oh + HH;
            const __nv_bfloat162 z(__nv_bfloat16(0.f), __nv_bfloat16(0.f));
            reinterpret_cast<__nv_bfloat162*>(oh)[0] = z;
            reinterpret_cast<__nv_bfloat162*>(oh)[1] = z;
            reinterpret_cast<__nv_bfloat162*>(ol)[0] = z;
            reinterpret_cast<__nv_bfloat162*>(ol)[1] = z;
        }
        return;
    }
    float4 v = reinterpret_cast<const float4*>(seq)[row * (HH / 4) + c4];
    __nv_bfloat16 h0, l0, h1, l1, h2, l2, h3, l3;
    split1(v.x, h0, l0); split1(v.y, h1, l1); split1(v.z, h2, l2); split1(v.w, h3, l3);
    __nv_bfloat16* oh = out + ((long)b * SS + r) * 2L * HH + c4 * 4;
    __nv_bfloat16* ol = oh + HH;
    reinterpret_cast<__nv_bfloat162*>(oh)[0] = __nv_bfloat162(h0, h1);
    reinterpret_cast<__nv_bfloat162*>(oh)[1] = __nv_bfloat162(h2, h3);
    reinterpret_cast<__nv_bfloat162*>(ol)[0] = __nv_bfloat162(l0, l1);
    reinterpret_cast<__nv_bfloat162*>(ol)[1] = __nv_bfloat162(l2, l3);
}

// ---------------------------------------------------------------------------
// Side-stream cat pass (overlaps the GEMMs): cat first half = mask ? seq : 0;
// masked rows additionally write cat second half = 0 and attn = colmean.
// All writes disjoint from GEMM5's unmasked-row scatter.
// ---------------------------------------------------------------------------
__launch_bounds__(256)
__global__ void cat_fill(const float* __restrict__ seq, const int* __restrict__ mask,
                         const float* __restrict__ cm,
                         float* __restrict__ cat, float* __restrict__ attn, int writeAttn)
{
    const long t = (long)blockIdx.x * 256 + threadIdx.x;
    const long total = (long)BB * SS * (HH / 4);
    if (t >= total) return;
    const long row = t / (HH / 4);
    const int c4 = (int)(t % (HH / 4));
    const int b = (int)(row >> 12);
    if (mask[row]) {
        float4 v = reinterpret_cast<const float4*>(seq)[row * (HH / 4) + c4];
        reinterpret_cast<float4*>(cat)[row * (2 * HH / 4) + c4] = v;
    } else {
        const float4 z = make_float4(0, 0, 0, 0);
        reinterpret_cast<float4*>(cat)[row * (2 * HH / 4) + c4] = z;
        reinterpret_cast<float4*>(cat)[row * (2 * HH / 4) + (HH / 4) + c4] = z;
        float4 v = reinterpret_cast<const float4*>(cm)[(long)b * (HH / 4) + c4];
        if (writeAttn)
            reinterpret_cast<float4*>(attn)[row * (HH / 4) + c4] = v;
    }
}

// ---------------------------------------------------------------------------
// Fused tgt pass: compacted tgt2 AND compacted vT2 with pad-slot zeroing.
// ---------------------------------------------------------------------------
__global__ void tgtv_prep(const float* __restrict__ V, const int* __restrict__ rnk,
                          const int* __restrict__ cnt_t,
                          __nv_bfloat16* __restrict__ tgt2, __nv_bfloat16* __restrict__ vT2)
{
    __shared__ float tile[32][33];
    const int b = blockIdx.z;
    const int ct = cnt_t[b];
    const int eRow = min((ct + 127) & ~127, TT);
    const int eCol = min((ct + 63) & ~63, TT);
    const int t0 = blockIdx.x * 32, h0 = blockIdx.y * 32;
    const int tx = threadIdx.x, ty = threadIdx.y;  // 32 x 8
    #pragma unroll
    for (int i = 0; i < 32; i += 8)
        tile[ty + i][tx] = V[((long)b * TT + t0 + ty + i) * HH + h0 + tx];
    __syncthreads();
    #pragma unroll
    for (int i = 0; i < 32; i += 8) {
        const int h = h0 + ty + i, t = t0 + tx;
        const int j = rnk[(long)b * TT + t];
        if (j >= 0) {
            __nv_bfloat16 hh, ll;
            split1(tile[tx][ty + i], hh, ll);
            const long base = ((long)b * HH + h) * (2L * TT) + j;
            vT2[base] = hh; vT2[base + TT] = ll;
        } else {
            const int slot = -j - 1;
            if (slot < eCol) {
                const long base = ((long)b * HH + h) * (2L * TT) + slot;
                vT2[base] = __nv_bfloat16(0.f); vT2[base + TT] = __nv_bfloat16(0.f);
            }
        }
    }
    #pragma unroll
    for (int i = 0; i < 32; i += 8) {
        const int t = t0 + ty + i;
        const int j = rnk[(long)b * TT + t];
        if (j >= 0) {
            __nv_bfloat16 hh, ll;
            split1(tile[ty + i][tx], hh, ll);
            __nv_bfloat16* o = tgt2 + ((long)b * TT + j) * 2L * HH + h0 + tx;
            o[0] = hh; o[HH] = ll;
        } else {
            const int slot = -j - 1;
            if (slot < eRow) {
                __nv_bfloat16* o = tgt2 + ((long)b * TT + slot) * 2L * HH + h0 + tx;
                o[0] = __nv_bfloat16(0.f); o[HH] = __nv_bfloat16(0.f);
            }
        }
    }
}

// ---------------------------------------------------------------------------
// W: fp32 -> split bf16
// ---------------------------------------------------------------------------
__launch_bounds__(256)
__global__ void split_plain(const float* __restrict__ in, __nv_bfloat16* __restrict__ out,
                            int R, int C)
{
    const long idx = (long)blockIdx.x * blockDim.x + threadIdx.x;
    const long total = (long)R * C / 4;
    if (idx >= total) return;
    const long row = idx / (C / 4);
    const int c4 = (int)(idx % (C / 4));
    float4 v = reinterpret_cast<const float4*>(in)[idx];
    __nv_bfloat16 h0, l0, h1, l1, h2, l2, h3, l3;
    split1(v.x, h0, l0); split1(v.y, h1, l1); split1(v.z, h2, l2); split1(v.w, h3, l3);
    __nv_bfloat16* oh = out + row * 2L * C + c4 * 4;
    __nv_bfloat16* ol = oh + C;
    reinterpret_cast<__nv_bfloat162*>(oh)[0] = __nv_bfloat162(h0, h1);
    reinterpret_cast<__nv_bfloat162*>(oh)[1] = __nv_bfloat162(h2, h3);
    reinterpret_cast<__nv_bfloat162*>(ol)[0] = __nv_bfloat162(l0, l1);
    reinterpret_cast<__nv_bfloat162*>(ol)[1] = __nv_bfloat162(l2, l3);
}

// ---------------------------------------------------------------------------
// colstat: cm = (1/T) sum_all V;  vm = sum over MASKED t of V.
// ---------------------------------------------------------------------------
__launch_bounds__(256)
__global__ void colstat(const float* __restrict__ V, const int* __restrict__ tmask,
                        float* __restrict__ cm, float* __restrict__ vm)
{
    const int t = blockIdx.x * 256 + threadIdx.x;
    if (t >= BB * HH) return;
    const int b = t / HH, h = t % HH;
    const float* p = V + (long)b * TT * HH + h;
    const int* m = tmask + (long)b * TT;
    float sa = 0.f, sm_ = 0.f;
    #pragma unroll 4
    for (int i = 0; i < TT; i++) {
        const float x = p[(long)i * HH];
        sa += x;
        if (!m[i]) sm_ += x;
    }
    cm[t] = sa * (1.0f / TT);
    vm[t] = sm_;
}

// ---------------------------------------------------------------------------
// HMMA GEMM (split-bf16 3-term). Compaction-aware; EPI1/2 take zOff so the
// batch range can be split across streams.
// ---------------------------------------------------------------------------
template <int EPI>
__launch_bounds__(256)
__global__ void gemm_mma(const __nv_bfloat16* __restrict__ A,
                         const __nv_bfloat16* __restrict__ Bm,
                         long aBatch, long bBatch, int C,
                         float* __restrict__ out0, float* __restrict__ out1,
                         __nv_bfloat16* __restrict__ obf,
                         int writeAttn,
                         const __nv_bfloat16* __restrict__ A2,
                         __nv_bfloat16* __restrict__ obf2, int ySplit,
                         const int* __restrict__ cntp, const int* __restrict__ cnt2p,
                         const int* __restrict__ idxp,
                         const float* __restrict__ cvec, const float* __restrict__ vmsum,
                         int zOff)
{
    extern __shared__ char smem[];
    const uint32_t sb = smem_u32(smem);

    const int tid = threadIdx.x;
    const int wid = tid >> 5;
    const int lane = tid & 31;

    const int z = blockIdx.z + zOff;
    const long Kr = 2L * C;

    const __nv_bfloat16* Ab;
    __nv_bfloat16* obf_sel = obf;
    long orow = 0;
    int m0, cb = SS;
    if (EPI == 0) {
        if ((int)blockIdx.y < ySplit) {
            const int b = blockIdx.y >> 5;
            m0 = (blockIdx.y & 31) * 128;
            if (m0 >= cntp[b]) return;
            Ab = A + (long)b * aBatch;
            orow = (long)b * SS;
        } else {
            const int yy = (int)blockIdx.y - ySplit;
            const int b = yy >> 2;
            m0 = (yy & 3) * 128;
            if (m0 >= cnt2p[b]) return;
            Ab = A2 + (long)b * bBatch;
            orow = (long)b * TT;
            obf_sel = obf2;
        }
    } else if (EPI == 1) {
        m0 = blockIdx.y * 128;
        cb = cntp[z];
        if (m0 >= cb) return;
        if ((int)blockIdx.x * 128 >= cnt2p[z]) return;
        Ab = A + (long)z * aBatch;
    } else {
        m0 = blockIdx.y * 128;
        cb = cntp[z];
        if (m0 >= cb) return;
        Ab = A + (long)z * aBatch;
    }
    const int n0 = blockIdx.x * 128;
    const __nv_bfloat16* Bb = Bm + (long)z * ((EPI == 0) ? 0 : bBatch);

    int kc;
    if (EPI == 2) kc = (cnt2p[z] + 63) >> 6;
    else          kc = C >> 6;
    const int nk = 3 * kc;

    const int vr0 = tid >> 3;
    const int vc16 = (tid & 7) * 16;

#define LDG_STAGE(IT, S)                                                          \
    {                                                                             \
        int _it = (IT);                                                           \
        int _seg = (_it >= 2 * kc) ? 2 : ((_it >= kc) ? 1 : 0);                   \
        int _kl = _it - _seg * kc;                                                \
        long _aC = ((_seg == 1) ? C : 0) + (long)_kl * 64 + (vc16 >> 1);          \
        long _bC = ((_seg == 2) ? C : 0) + (long)_kl * 64 + (vc16 >> 1);          \
        uint32_t _sA = sb + (S) * 32768u;                                         \
        uint32_t _sB = _sA + 16384u;                                              \
        _Pragma("unroll")                                                         \
        for (int i = 0; i < 4; i++) {                                             \
            int r = vr0 + 32 * i;                                                 \
            uint32_t sw = (uint32_t)(r * 128 + (vc16 ^ ((r & 7) << 4)));          \
            cp16(_sA + sw, Ab + (long)(m0 + r) * Kr + _aC);                       \
            cp16(_sB + sw, Bb + (long)(n0 + r) * Kr + _bC);                       \
        }                                                                         \
    }

    LDG_STAGE(0, 0); CP_COMMIT();
    LDG_STAGE(1, 1); CP_COMMIT();

    const int wm = wid & 1;
    const int wn = wid >> 1;

    float acc[4][4][4] = {};

    const int arow = wm * 64 + (lane & 15);
    const int akb = (lane >> 4) * 16;
    const int brow = wn * 32 + (lane & 7) + ((lane >> 4) * 8);
    const int bkb = ((lane >> 3) & 1) * 16;

    for (int it = 0; it < nk; it++) {
        if (it + 1 < nk) cp_wait<1>(); else cp_wait<0>();
        __syncthreads();

        const uint32_t stA = sb + (uint32_t)(it % 3) * 32768u;
        const uint32_t stB = stA + 16384u;

        #pragma unroll
        for (int ks = 0; ks < 4; ks++) {
            uint32_t afr[4][4], bfr[2][4];
            #pragma unroll
            for (int mt = 0; mt < 4; mt++) {
                const int row = arow + mt * 16;
                ldsm_x4(afr[mt], stA + row * 128 + ((ks * 32 + akb) ^ ((row & 7) << 4)));
            }
            #pragma unroll
            for (int ntp = 0; ntp < 2; ntp++) {
                const int row = brow + ntp * 16;
                ldsm_x4(bfr[ntp], stB + row * 128 + ((ks * 32 + bkb) ^ ((row & 7) << 4)));
            }
            #pragma unroll
            for (int mt = 0; mt < 4; mt++)
                #pragma unroll
                for (int nt = 0; nt < 4; nt++)
                    mma_bf16(acc[mt][nt], afr[mt], &bfr[nt >> 1][(nt & 1) * 2]);
        }

        if (it + 2 < nk) { LDG_STAGE(it + 2, (it + 2) % 3); CP_COMMIT(); }
    }

    // ---- epilogue ----
    const int er = wm * 64 + (lane >> 2);
    const int ec = wn * 32 + (lane & 3) * 2;

    if (EPI == 0) {
        const int Nout = gridDim.x * 128;
        #pragma unroll
        for (int mt = 0; mt < 4; mt++)
            #pragma unroll
            for (int nt = 0; nt < 4; nt++)
                #pragma unroll
                for (int h = 0; h < 2; h++) {
                    const long row = orow + m0 + er + mt * 16 + h * 8;
                    const int col = n0 + ec + nt * 8;
                    float x0 = fmaxf(acc[mt][nt][2 * h], 0.f);
                    float x1 = fmaxf(acc[mt][nt][2 * h + 1], 0.f);
                    __nv_bfloat16 h0, l0, h1, l1;
                    split1(x0, h0, l0); split1(x1, h1, l1);
                    __nv_bfloat16* oh = obf_sel + row * 2 * Nout + col;
                    *reinterpret_cast<__nv_bfloat162*>(oh) = __nv_bfloat162(h0, h1);
                    *reinterpret_cast<__nv_bfloat162*>(oh + Nout) = __nv_bfloat162(l0, l1);
                }
    } else if (EPI == 1) {
        #pragma unroll
        for (int mt = 0; mt < 4; mt++)
            #pragma unroll
            for (int nt = 0; nt < 4; nt++)
                #pragma unroll
                for (int h = 0; h < 2; h++) {
                    const int row = m0 + er + mt * 16 + h * 8;
                    const int col = n0 + ec + nt * 8;
                    float2 v = make_float2(acc[mt][nt][2 * h], acc[mt][nt][2 * h + 1]);
                    *reinterpret_cast<float2*>(out0 + ((long)z * SS + row) * TT + col) = v;
                }
    } else {
        const long zb = (long)z * SS;
        #pragma unroll
        for (int mt = 0; mt < 4; mt++)
            #pragma unroll
            for (int h = 0; h < 2; h++) {
                const int local = m0 + er + mt * 16 + h * 8;
                if (local < cb) {
                    const float cr = cvec[zb + local];
                    const long gs = zb + idxp[zb + local];
                    #pragma unroll
                    for (int nt = 0; nt < 4; nt++) {
                        const int col = n0 + ec + nt * 8;
                        const float2 w = *reinterpret_cast<const float2*>(
                            vmsum + (long)z * HH + col);
                        float2 v = make_float2(acc[mt][nt][2 * h] + cr * w.x,
                                               acc[mt][nt][2 * h + 1] + cr * w.y);
                        if (writeAttn)
                            *reinterpret_cast<float2*>(out1 + gs * (long)HH + col) = v;
                        *reinterpret_cast<float2*>(out0 + gs * (long)(2 * HH) + HH + col) = v;
                    }
                }
            }
    }
#undef LDG_STAGE
}

// ---------------------------------------------------------------------------
// Softmax on compacted logits; rowOff allows batch-range splitting.
// ---------------------------------------------------------------------------
__launch_bounds__(128)
__global__ void softmax_c(const float* __restrict__ logits, __nv_bfloat16* __restrict__ P2,
                          float* __restrict__ cvec,
                          const int* __restrict__ cnt_s, const int* __restrict__ cnt_t,
                          long rowOff)
{
    const long row = blockIdx.x + rowOff;
    const int b = (int)(row >> 12);
    if ((int)(row & (SS - 1)) >= cnt_s[b]) return;
    const int ct = cnt_t[b];
    const int kpad = (ct + 63) & ~63;
    const float* p = logits + row * TT;
    const int tid = threadIdx.x;
    const int warp = tid >> 5, lane = tid & 31;

    float v[4];
    #pragma unroll
    for (int i = 0; i < 4; i++) {
        const int j = tid + 128 * i;
        v[i] = (j < ct) ? p[j] : -1e30f;
    }

    float mx = fmaxf(fmaxf(v[0], v[1]), fmaxf(v[2], v[3]));
    #pragma unroll
    for (int o = 16; o > 0; o >>= 1) mx = fmaxf(mx, __shfl_xor_sync(0xffffffffu, mx, o));
    __shared__ float smx[4];
    if (lane == 0) smx[warp] = mx;
    __syncthreads();
    mx = fmaxf(fmaxf(smx[0], smx[1]), fmaxf(smx[2], smx[3]));
    if (ct < TT) mx = fmaxf(mx, 0.0f);

    float sum = 0.f;
    #pragma unroll
    for (int i = 0; i < 4; i++) {
        const int j = tid + 128 * i;
        if (j < ct) { v[i] = __expf(v[i] - mx); sum += v[i]; }
    }
    #pragma unroll
    for (int o = 16; o > 0; o >>= 1) sum += __shfl_xor_sync(0xffffffffu, sum, o);
    __shared__ float ssum[4];
    if (lane == 0) ssum[warp] = sum;
    __syncthreads();
    const float em = __expf(-mx);
    const float inv = 1.0f / (ssum[0] + ssum[1] + ssum[2] + ssum[3] + (float)(TT - ct) * em);

    if (tid == 0) cvec[row] = em * inv;

    __nv_bfloat16* out = P2 + row * 2L * TT;
    #pragma unroll
    for (int i = 0; i < 4; i++) {
        const int j = tid + 128 * i;
        if (j < ct) {
            __nv_bfloat16 h, l;
            split1(v[i] * inv, h, l);
            out[j] = h; out[TT + j] = l;
        } else if (j < kpad) {
            out[j] = __nv_bfloat16(0.f); out[TT + j] = __nv_bfloat16(0.f);
        }
    }
}

// ---------------------------------------------------------------------------
// One-time side streams/events for graph forking.
// ---------------------------------------------------------------------------
static cudaStream_t g_s1 = nullptr, g_s2 = nullptr;
static cudaEvent_t g_e0 = nullptr, g_e1 = nullptr, g_e2a = nullptr, g_e2b = nullptr;
static cudaEvent_t g_eG0 = nullptr, g_e5b = nullptr;

extern "C" void kernel_launch(void* const* d_in, const int* in_sizes, int n_in,
                              void* d_out, int out_size)
{
    const float* seq   = (const float*)d_in[0];
    const int*   smask = (const int*)d_in[1];
    const float* tgt   = (const float*)d_in[2];
    const int*   tmask = (const int*)d_in[3];
    const float* W     = (const float*)d_in[4];
    float* out = (float*)d_out;

    if (!g_s1) {
        cudaStreamCreateWithFlags(&g_s1, cudaStreamNonBlocking);
        cudaStreamCreateWithFlags(&g_s2, cudaStreamNonBlocking);
        cudaEventCreateWithFlags(&g_e0, cudaEventDisableTiming);
        cudaEventCreateWithFlags(&g_e1, cudaEventDisableTiming);
        cudaEventCreateWithFlags(&g_e2a, cudaEventDisableTiming);
        cudaEventCreateWithFlags(&g_e2b, cudaEventDisableTiming);
        cudaEventCreateWithFlags(&g_eG0, cudaEventDisableTiming);
        cudaEventCreateWithFlags(&g_e5b, cudaEventDisableTiming);
    }

    __nv_bfloat16 *p_seq2, *p_tgt2, *p_W2, *p_seqt2, *p_tgtt2, *p_probs2, *p_vT2;
    float *p_logits, *p_cm, *p_vm, *p_c;
    int *p_idx_s, *p_rnk_s, *p_cnt_s, *p_idx_t, *p_rnk_t, *p_cnt_t;
    cudaGetSymbolAddress((void**)&p_seq2, g_seq2);
    cudaGetSymbolAddress((void**)&p_tgt2, g_tgt2);
    cudaGetSymbolAddress((void**)&p_W2, g_W2);
    cudaGetSymbolAddress((void**)&p_seqt2, g_seqt2);
    cudaGetSymbolAddress((void**)&p_tgtt2, g_tgtt2);
    cudaGetSymbolAddress((void**)&p_logits, g_logits);
    cudaGetSymbolAddress((void**)&p_probs2, g_probs2);
    cudaGetSymbolAddress((void**)&p_vT2, g_vT2);
    cudaGetSymbolAddress((void**)&p_idx_s, g_idx_s);
    cudaGetSymbolAddress((void**)&p_rnk_s, g_rnk_s);
    cudaGetSymbolAddress((void**)&p_cnt_s, g_cnt_s);
    cudaGetSymbolAddress((void**)&p_idx_t, g_idx_t);
    cudaGetSymbolAddress((void**)&p_rnk_t, g_rnk_t);
    cudaGetSymbolAddress((void**)&p_cnt_t, g_cnt_t);
    cudaGetSymbolAddress((void**)&p_cm, g_cm);
    cudaGetSymbolAddress((void**)&p_vm, g_vm);
    cudaGetSymbolAddress((void**)&p_c, g_c);

    const int write_attn = (out_size >= BB * SS * 3 * HH) ? 1 : 0;
    float* out_attn = out + (size_t)BB * SS * 2 * HH;

    const int SMEM_DYN = 3 * 32768;
    cudaFuncSetAttribute(gemm_mma<0>, cudaFuncAttributeMaxDynamicSharedMemorySize, SMEM_DYN);
    cudaFuncSetAttribute(gemm_mma<1>, cudaFuncAttributeMaxDynamicSharedMemorySize, SMEM_DYN);
    cudaFuncSetAttribute(gemm_mma<2>, cudaFuncAttributeMaxDynamicSharedMemorySize, SMEM_DYN);

    const int NCHUNK_S = (BB * SS * (HH / 4) + 255) / 256;
    const int HB = BB / 2;   // batches per chain

    // ---- fork ----
    cudaEventRecord(g_e0, 0);
    cudaStreamWaitEvent(g_s1, g_e0, 0);
    cudaStreamWaitEvent(g_s2, g_e0, 0);

    // stream0 (long pole): seq compaction + slimmed seq prep
    compact_index<<<BB, 1024>>>(smask, p_idx_s, p_rnk_s, p_cnt_s, SS);
    seq_prep<<<NCHUNK_S, 256>>>(seq, p_rnk_s, p_cnt_s, p_seq2);

    // s1: tgt compaction + tgt/vT prep
    compact_index<<<BB, 1024, 0, g_s1>>>(tmask, p_idx_t, p_rnk_t, p_cnt_t, TT);
    tgtv_prep<<<dim3(TT / 32, HH / 32, BB), dim3(32, 8), 0, g_s1>>>(
        tgt, p_rnk_t, p_cnt_t, p_tgt2, p_vT2);
    cudaEventRecord(g_e1, g_s1);

    // s2: W split + colstat, then cat_fill (overlaps the GEMM chain)
    split_plain<<<(HH * HH / 4 + 255) / 256, 256, 0, g_s2>>>(W, p_W2, HH, HH);
    colstat<<<(BB * HH + 255) / 256, 256, 0, g_s2>>>(tgt, tmask, p_cm, p_vm);
    cudaEventRecord(g_e2a, g_s2);
    cat_fill<<<NCHUNK_S, 256, 0, g_s2>>>(seq, smask, p_cm, out, out_attn, write_attn);
    cudaEventRecord(g_e2b, g_s2);

    // join prep results needed by the GEMM chain
    cudaStreamWaitEvent(0, g_e1, 0);
    cudaStreamWaitEvent(0, g_e2a, 0);

    // 1+2 merged) seq_t AND tgt_t = relu(X @ W^T), both compacted
    const int Y_SEQ = (BB * SS) / 128;   // 256
    const int Y_TGT = (BB * TT) / 128;   // 32
    gemm_mma<0><<<dim3(HH / 128, Y_SEQ + Y_TGT, 1), 256, SMEM_DYN>>>(
        p_seq2, p_W2, (long)SS * 2 * HH, (long)TT * 2 * HH, HH,
        nullptr, nullptr, p_seqt2, 0,
        p_tgt2, p_tgtt2, Y_SEQ, p_cnt_s, p_cnt_t, nullptr, nullptr, nullptr, 0);
    cudaEventRecord(g_eG0, 0);
    cudaStreamWaitEvent(g_s1, g_eG0, 0);

    // ---- dual chains: batches [0,HB) on stream0, [HB,BB) on s1 ----
    // chain A (stream0)
    gemm_mma<1><<<dim3(TT / 128, SS / 128, HB), 256, SMEM_DYN>>>(
        p_seqt2, p_tgtt2, (long)SS * 2 * HH, (long)TT * 2 * HH, HH,
        p_logits, nullptr, nullptr, 0, nullptr, nullptr, 1 << 30,
        p_cnt_s, p_cnt_t, nullptr, nullptr, nullptr, 0);
    softmax_c<<<HB * SS, 128>>>(p_logits, p_probs2, p_c, p_cnt_s, p_cnt_t, 0L);
    gemm_mma<2><<<dim3(HH / 128, SS / 128, HB), 256, SMEM_DYN>>>(
        p_probs2, p_vT2, (long)SS * 2 * TT, (long)HH * 2 * TT, TT,
        out, out_attn, nullptr, write_attn, nullptr, nullptr, 1 << 30,
        p_cnt_s, p_cnt_t, p_idx_s, p_c, p_vm, 0);

    // chain B (s1)
    gemm_mma<1><<<dim3(TT / 128, SS / 128, HB), 256, SMEM_DYN, g_s1>>>(
        p_seqt2, p_tgtt2, (long)SS * 2 * HH, (long)TT * 2 * HH, HH,
        p_logits, nullptr, nullptr, 0, nullptr, nullptr, 1 << 30,
        p_cnt_s, p_cnt_t, nullptr, nullptr, nullptr, HB);
    softmax_c<<<HB * SS, 128, 0, g_s1>>>(p_logits, p_probs2, p_c, p_cnt_s, p_cnt_t,
                                         (long)HB * SS);
    gemm_mma<2><<<dim3(HH / 128, SS / 128, HB), 256, SMEM_DYN, g_s1>>>(
        p_probs2, p_vT2, (long)SS * 2 * TT, (long)HH * 2 * TT, TT,
        out, out_attn, nullptr, write_attn, nullptr, nullptr, 1 << 30,
        p_cnt_s, p_cnt_t, p_idx_s, p_c, p_vm, HB);
    cudaEventRecord(g_e5b, g_s1);

    // join everything
    cudaStreamWaitEvent(0, g_e5b, 0);
    cudaStreamWaitEvent(0, g_e2b, 0);
}